// round 13
// baseline (speedup 1.0000x reference)
#include <cuda_runtime.h>
#include <cuda_bf16.h>
#include <math.h>
#include <stdint.h>

// Problem constants
#define BB 2
#define TT 2048
#define DD 2048
#define HH 16
#define KD 128
#define VD 128
#define BT (BB*TT)          // 4096
#define HK (HH*KD)          // 2048
#define HV (HH*VD)          // 2048

// ---------------- scratch ----------------
__device__ float g_Q[BT*HK];
__device__ float g_K[BT*HK];
__device__ float g_V[BT*HV];
__device__ float g_Qc[BT*HK];
__device__ float g_Kc[BT*HK];
__device__ float g_Vc[BT*HV];
__device__ float g_EG[BT*HK];
__device__ float g_Gate[BT*HV];
__device__ float g_Beta[BT*HH];
__device__ float g_Y[BT*HV];

__device__ __nv_bfloat16 g_xh[BT*DD],  g_xl[BT*DD];
__device__ __nv_bfloat16 g_Yh[BT*HV],  g_Yl[BT*HV];
__device__ __nv_bfloat16 g_F1h[BT*VD], g_F1l[BT*VD];
__device__ __nv_bfloat16 g_G1h[BT*VD], g_G1l[BT*VD];
__device__ __nv_bfloat16 g_Wqh[HK*DD], g_Wql[HK*DD];
__device__ __nv_bfloat16 g_Wkh[HK*DD], g_Wkl[HK*DD];
__device__ __nv_bfloat16 g_Wvh[HV*DD], g_Wvl[HV*DD];
__device__ __nv_bfloat16 g_Woh[DD*HV], g_Wol[DD*HV];
__device__ __nv_bfloat16 g_Wf1h[VD*DD], g_Wf1l[VD*DD];
__device__ __nv_bfloat16 g_Wg1h[VD*DD], g_Wg1l[VD*DD];
__device__ __nv_bfloat16 g_Wf2h[HK*VD], g_Wf2l[HK*VD];
__device__ __nv_bfloat16 g_Wg2h[HV*VD], g_Wg2l[HV*VD];

// ================= helpers =================
#define SWZ(off) ((off) ^ (((off) >> 3) & 0x70))

__device__ __forceinline__ uint32_t sm2u(const void* p) {
    uint32_t a;
    asm("{ .reg .u64 t; cvta.to.shared.u64 t, %1; cvt.u32.u64 %0, t; }" : "=r"(a) : "l"(p));
    return a;
}

#define CP_ASYNC16(dst, src) \
    asm volatile("cp.async.cg.shared.global [%0], [%1], 16;" :: "r"(dst), "l"(src))
#define CP_COMMIT() asm volatile("cp.async.commit_group;")
#define CP_WAIT1()  asm volatile("cp.async.wait_group 1;")
#define CP_WAIT0()  asm volatile("cp.async.wait_group 0;")

#define LDMAT4(r0, r1, r2, r3, addr) \
    asm volatile("ldmatrix.sync.aligned.m8n8.x4.shared.b16 {%0,%1,%2,%3}, [%4];" \
        : "=r"(r0), "=r"(r1), "=r"(r2), "=r"(r3) : "r"(addr))

#define MMA_BF16(d, a, b) \
    asm volatile("mma.sync.aligned.m16n8k16.row.col.f32.bf16.bf16.f32 " \
        "{%0,%1,%2,%3},{%4,%5,%6,%7},{%8,%9},{%0,%1,%2,%3};" \
        : "+f"((d)[0]), "+f"((d)[1]), "+f"((d)[2]), "+f"((d)[3]) \
        : "r"((a)[0]), "r"((a)[1]), "r"((a)[2]), "r"((a)[3]), "r"((b)[0]), "r"((b)[1]))

// packed f32x2 ops
#define FMA2(d, a, b) asm("fma.rn.f32x2 %0, %1, %2, %0;" : "+l"(d) : "l"(a), "l"(b))
#define MUL2(d, a, b) asm("mul.rn.f32x2 %0, %1, %2;" : "=l"(d) : "l"(a), "l"(b))

__device__ __forceinline__ uint64_t pack2(float x, float y) {
    uint64_t r; asm("mov.b64 %0, {%1, %2};" : "=l"(r) : "f"(x), "f"(y)); return r;
}
__device__ __forceinline__ float2 unpack2(uint64_t v) {
    float x, y; asm("mov.b64 {%0, %1}, %2;" : "=f"(x), "=f"(y) : "l"(v));
    return make_float2(x, y);
}

struct BatchArgs {
    const __nv_bfloat16* Ah[3];
    const __nv_bfloat16* Al[3];
    const __nv_bfloat16* Bh[3];
    const __nv_bfloat16* Bl[3];
    float* C[3];
    __nv_bfloat16* Ch[3];
    __nv_bfloat16* Cl[3];
    int mode[3];
    const float* A_log;
    const float* dtb;
    int N, Kd;
};

// common epilogue
template<int NT>
__device__ __forceinline__ void gemm_epilogue(const BatchArgs& args, int z,
                                              float acc[][NT][4], int MT,
                                              int m0, int n0, int mrowbase,
                                              int nw, int lane, int N)
{
    float* __restrict__ C = args.C[z];
    __nv_bfloat16* __restrict__ Ch = args.Ch[z];
    __nv_bfloat16* __restrict__ Cl = args.Cl[z];
    const int mode = args.mode[z];
    for (int mt = 0; mt < MT; mt++)
#pragma unroll
        for (int nt = 0; nt < NT; nt++) {
            int r = m0 + mrowbase + mt * 16 + (lane >> 2);
            int c = n0 + nw * NT * 8 + nt * 8 + (lane & 3) * 2;
#pragma unroll
            for (int half = 0; half < 2; half++) {
                int rr = r + half * 8;
                float v0 = acc[mt][nt][half * 2 + 0];
                float v1 = acc[mt][nt][half * 2 + 1];
                size_t off = (size_t)rr * N + c;
                if (mode == 0) {
                    *(float2*)&C[off] = make_float2(v0, v1);
                } else if (mode == 1) {
                    __nv_bfloat16 h0 = __float2bfloat16(v0);
                    __nv_bfloat16 h1 = __float2bfloat16(v1);
                    __nv_bfloat162 hh; hh.x = h0; hh.y = h1;
                    __nv_bfloat162 ll;
                    ll.x = __float2bfloat16(v0 - __bfloat162float(h0));
                    ll.y = __float2bfloat16(v1 - __bfloat162float(h1));
                    *(__nv_bfloat162*)&Ch[off] = hh;
                    *(__nv_bfloat162*)&Cl[off] = ll;
                } else {
                    int h = c >> 7;
                    float ea = expf(args.A_log[h]);
                    float x0 = v0 + args.dtb[c], x1 = v1 + args.dtb[c + 1];
                    float sp0 = (x0 > 20.f) ? x0 : log1pf(expf(x0));
                    float sp1 = (x1 > 20.f) ? x1 : log1pf(expf(x1));
                    *(float2*)&C[off] = make_float2(expf(-ea * sp0), expf(-ea * sp1));
                }
            }
        }
}

// ===== 256-thread variant (8 warps 2x4, mt=4, 3-stage) — best for K=2048 =====
template<int NT>
__global__ __launch_bounds__(256, 1) void mmagemmA(const BatchArgs args)
{
    constexpr int BN  = NT * 32;
    constexpr int WN  = NT * 8;
    constexpr int ASZ = 128 * 128;
    constexpr int BSZ = BN * 128;
    constexpr int STG = 2 * ASZ + 2 * BSZ;
    extern __shared__ __align__(1024) char smem[];
    const uint32_t sb = sm2u(smem);
    const int tid = threadIdx.x;
    const int z = blockIdx.z;
    const int m0 = blockIdx.y * 128, n0 = blockIdx.x * BN;
    const int N = args.N, Kd = args.Kd;

    const __nv_bfloat16* __restrict__ Ah = args.Ah[z];
    const __nv_bfloat16* __restrict__ Al = args.Al[z];
    const __nv_bfloat16* __restrict__ Bh = args.Bh[z];
    const __nv_bfloat16* __restrict__ Bl = args.Bl[z];

    auto prefetch = [&](int stg, int k0) {
        uint32_t b = sb + stg * STG;
        for (int idx = tid; idx < 1024; idx += 256) {
            int row = idx >> 3, ck = idx & 7;
            size_t go = ((size_t)(m0 + row) * Kd + k0) * 2 + ck * 16;
            uint32_t so = b + SWZ(row * 128 + ck * 16);
            CP_ASYNC16(so,       (const char*)Ah + go);
            CP_ASYNC16(so + ASZ, (const char*)Al + go);
        }
        for (int idx = tid; idx < BN * 8; idx += 256) {
            int row = idx >> 3, ck = idx & 7;
            size_t go = ((size_t)(n0 + row) * Kd + k0) * 2 + ck * 16;
            uint32_t so = b + 2 * ASZ + SWZ(row * 128 + ck * 16);
            CP_ASYNC16(so,       (const char*)Bh + go);
            CP_ASYNC16(so + BSZ, (const char*)Bl + go);
        }
    };

    const int wid = tid >> 5, lane = tid & 31;
    const int mw = wid >> 2, nw = wid & 3;
    const uint32_t xm = (lane & 7) * 16;
    const int arow = mw * 64 + (lane & 15);
    const int asel = ((lane >> 4) & 1) << 4;
    const int brow = nw * WN + (lane & 7) + (((lane >> 4) & 1) << 3);
    const int bsel = ((lane >> 3) & 1) << 4;

    float acc[4][NT][4];
#pragma unroll
    for (int mt = 0; mt < 4; mt++)
#pragma unroll
        for (int nt = 0; nt < NT; nt++)
#pragma unroll
            for (int q = 0; q < 4; q++) acc[mt][nt][q] = 0.f;

    const int iters = Kd >> 6;
    prefetch(0, 0);
    CP_COMMIT();
    if (iters > 1) { prefetch(1, 64); }
    CP_COMMIT();
    CP_WAIT1();
    __syncthreads();

    int stg = 0;
    for (int it = 0; it < iters; it++) {
        if (it + 2 < iters) {
            int ns = stg + 2; if (ns >= 3) ns -= 3;
            prefetch(ns, (it + 2) * 64);
            CP_COMMIT();
        }

        const uint32_t b = sb + stg * STG;
#pragma unroll
        for (int kk = 0; kk < 4; kk++) {
            const int koff = kk * 32;
            uint32_t ah[4][4], al[4][4];
#pragma unroll
            for (int mt = 0; mt < 4; mt++) {
                uint32_t ad = b + (uint32_t)(arow + mt * 16) * 128 + ((koff + asel) ^ xm);
                LDMAT4(ah[mt][0], ah[mt][1], ah[mt][2], ah[mt][3], ad);
                LDMAT4(al[mt][0], al[mt][1], al[mt][2], al[mt][3], ad + ASZ);
            }
            uint32_t bh[NT][2], bl[NT][2];
#pragma unroll
            for (int j = 0; j < NT / 2; j++) {
                uint32_t bd = b + 2 * ASZ + (uint32_t)(brow + j * 16) * 128 + ((koff + bsel) ^ xm);
                LDMAT4(bh[2*j][0], bh[2*j][1], bh[2*j+1][0], bh[2*j+1][1], bd);
                LDMAT4(bl[2*j][0], bl[2*j][1], bl[2*j+1][0], bl[2*j+1][1], bd + BSZ);
            }
#pragma unroll
            for (int mt = 0; mt < 4; mt++)
#pragma unroll
                for (int nt = 0; nt < NT; nt++) {
                    MMA_BF16(acc[mt][nt], ah[mt], bh[nt]);
                    MMA_BF16(acc[mt][nt], ah[mt], bl[nt]);
                    MMA_BF16(acc[mt][nt], al[mt], bh[nt]);
                }
        }

        if (it + 1 < iters) { CP_WAIT1(); }
        __syncthreads();
        stg++; if (stg == 3) stg = 0;
    }

    gemm_epilogue<NT>(args, z, acc, 4, m0, n0, mw * 64, nw, lane, N);
}

// ===== 512-thread variant (16 warps 4x4, mt=2, 3-stage) — best for K=128 =====
template<int NT>
__global__ __launch_bounds__(512, 1) void mmagemmB(const BatchArgs args)
{
    constexpr int BN  = NT * 32;
    constexpr int WN  = NT * 8;
    constexpr int ASZ = 128 * 128;
    constexpr int BSZ = BN * 128;
    constexpr int STG = 2 * ASZ + 2 * BSZ;
    extern __shared__ __align__(1024) char smem[];
    const uint32_t sb = sm2u(smem);
    const int tid = threadIdx.x;
    const int z = blockIdx.z;
    const int m0 = blockIdx.y * 128, n0 = blockIdx.x * BN;
    const int N = args.N, Kd = args.Kd;

    const __nv_bfloat16* __restrict__ Ah = args.Ah[z];
    const __nv_bfloat16* __restrict__ Al = args.Al[z];
    const __nv_bfloat16* __restrict__ Bh = args.Bh[z];
    const __nv_bfloat16* __restrict__ Bl = args.Bl[z];

    auto prefetch = [&](int stg, int k0) {
        uint32_t b = sb + stg * STG;
#pragma unroll
        for (int idx = tid; idx < 1024; idx += 512) {
            int row = idx >> 3, ck = idx & 7;
            size_t go = ((size_t)(m0 + row) * Kd + k0) * 2 + ck * 16;
            uint32_t so = b + SWZ(row * 128 + ck * 16);
            CP_ASYNC16(so,       (const char*)Ah + go);
            CP_ASYNC16(so + ASZ, (const char*)Al + go);
        }
        for (int idx = tid; idx < BN * 8; idx += 512) {
            int row = idx >> 3, ck = idx & 7;
            size_t go = ((size_t)(n0 + row) * Kd + k0) * 2 + ck * 16;
            uint32_t so = b + 2 * ASZ + SWZ(row * 128 + ck * 16);
            CP_ASYNC16(so,       (const char*)Bh + go);
            CP_ASYNC16(so + BSZ, (const char*)Bl + go);
        }
    };

    const int wid = tid >> 5, lane = tid & 31;
    const int mw = wid >> 2, nw = wid & 3;
    const uint32_t xm = (lane & 7) * 16;
    const int arow = mw * 32 + (lane & 15);
    const int asel = ((lane >> 4) & 1) << 4;
    const int brow = nw * WN + (lane & 7) + (((lane >> 4) & 1) << 3);
    const int bsel = ((lane >> 3) & 1) << 4;

    float acc[2][NT][4];
#pragma unroll
    for (int mt = 0; mt < 2; mt++)
#pragma unroll
        for (int nt = 0; nt < NT; nt++)
#pragma unroll
            for (int q = 0; q < 4; q++) acc[mt][nt][q] = 0.f;

    const int iters = Kd >> 6;
    prefetch(0, 0);
    CP_COMMIT();
    if (iters > 1) { prefetch(1, 64); }
    CP_COMMIT();
    CP_WAIT1();
    __syncthreads();

    int stg = 0;
    for (int it = 0; it < iters; it++) {
        if (it + 2 < iters) {
            int ns = stg + 2; if (ns >= 3) ns -= 3;
            prefetch(ns, (it + 2) * 64);
            CP_COMMIT();
        }

        const uint32_t b = sb + stg * STG;
#pragma unroll
        for (int kk = 0; kk < 4; kk++) {
            const int koff = kk * 32;
            uint32_t ah[2][4], al[2][4];
#pragma unroll
            for (int mt = 0; mt < 2; mt++) {
                uint32_t ad = b + (uint32_t)(arow + mt * 16) * 128 + ((koff + asel) ^ xm);
                LDMAT4(ah[mt][0], ah[mt][1], ah[mt][2], ah[mt][3], ad);
                LDMAT4(al[mt][0], al[mt][1], al[mt][2], al[mt][3], ad + ASZ);
            }
            uint32_t bh[NT][2], bl[NT][2];
#pragma unroll
            for (int j = 0; j < NT / 2; j++) {
                uint32_t bd = b + 2 * ASZ + (uint32_t)(brow + j * 16) * 128 + ((koff + bsel) ^ xm);
                LDMAT4(bh[2*j][0], bh[2*j][1], bh[2*j+1][0], bh[2*j+1][1], bd);
                LDMAT4(bl[2*j][0], bl[2*j][1], bl[2*j+1][0], bl[2*j+1][1], bd + BSZ);
            }
#pragma unroll
            for (int mt = 0; mt < 2; mt++)
#pragma unroll
                for (int nt = 0; nt < NT; nt++) {
                    MMA_BF16(acc[mt][nt], ah[mt], bh[nt]);
                    MMA_BF16(acc[mt][nt], ah[mt], bl[nt]);
                    MMA_BF16(acc[mt][nt], al[mt], bh[nt]);
                }
        }

        if (it + 1 < iters) { CP_WAIT1(); }
        __syncthreads();
        stg++; if (stg == 3) stg = 0;
    }

    gemm_epilogue<NT>(args, z, acc, 2, m0, n0, mw * 32, nw, lane, N);
}

// ---------------- fused segmented split ----------------
struct SplitArgs {
    const float4* src[9];
    __nv_bfloat162* h[9];
    __nv_bfloat162* l[9];
    int end[9];
};

__global__ void splitall_kernel(const SplitArgs a)
{
    int bid = blockIdx.x;
    int seg = 0;
#pragma unroll
    for (int i = 0; i < 8; i++)
        if (bid >= a.end[i]) seg = i + 1;
    int start = (seg == 0) ? 0 : a.end[seg - 1];
    int i4 = (bid - start) * 256 + threadIdx.x;
    float4 v = a.src[seg][i4];
    __nv_bfloat16 hx = __float2bfloat16(v.x), hy = __float2bfloat16(v.y);
    __nv_bfloat16 hz = __float2bfloat16(v.z), hw = __float2bfloat16(v.w);
    __nv_bfloat162 p0, p1, q0, q1;
    p0.x = hx; p0.y = hy; p1.x = hz; p1.y = hw;
    q0.x = __float2bfloat16(v.x - __bfloat162float(hx));
    q0.y = __float2bfloat16(v.y - __bfloat162float(hy));
    q1.x = __float2bfloat16(v.z - __bfloat162float(hz));
    q1.y = __float2bfloat16(v.w - __bfloat162float(hw));
    a.h[seg][i4 * 2] = p0; a.h[seg][i4 * 2 + 1] = p1;
    a.l[seg][i4 * 2] = q0; a.l[seg][i4 * 2 + 1] = q1;
}

// ---------------- beta = sigmoid(x @ Wb^T), 8 rows per block (Wb L1 reuse) ----------------
__global__ __launch_bounds__(256) void beta_kernel(const float* __restrict__ x,
                                                   const float* __restrict__ Wb,
                                                   float* __restrict__ Beta)
{
    const int tid = threadIdx.x;
    const int warp = tid >> 5, lane = tid & 31;
    __shared__ float red[HH][9];

    for (int r = 0; r < 8; r++) {
        const int m = blockIdx.x * 8 + r;
        if (r > 0) __syncthreads();
        float acc[HH];
#pragma unroll
        for (int h = 0; h < HH; h++) acc[h] = 0.f;
        for (int d = tid; d < DD; d += 256) {
            float xv = x[(size_t)m * DD + d];
#pragma unroll
            for (int h = 0; h < HH; h++)
                acc[h] = fmaf(xv, Wb[(size_t)h * DD + d], acc[h]);
        }
#pragma unroll
        for (int h = 0; h < HH; h++) {
            float v = acc[h];
#pragma unroll
            for (int mask = 16; mask > 0; mask >>= 1)
                v += __shfl_xor_sync(0xffffffffu, v, mask);
            if (lane == 0) red[h][warp] = v;
        }
        __syncthreads();
        if (tid < HH) {
            float s = 0.f;
#pragma unroll
            for (int w = 0; w < 8; w++) s += red[tid][w];
            Beta[(size_t)m * HH + tid] = 1.f / (1.f + expf(-s));
        }
    }
}

// ---------------- causal depthwise conv (k=4) + silu (+ optional l2norm) ----------------
__global__ __launch_bounds__(128) void convnorm_kernel(const float* __restrict__ in,
                                                       const float* __restrict__ w,
                                                       float* __restrict__ out,
                                                       int doNorm)
{
    const int m = blockIdx.x >> 4;
    const int h = blockIdx.x & 15;
    const int t = m & (TT - 1);
    const int c = threadIdx.x;
    const int col = h * 128 + c;
    const float* wp = &w[(size_t)(h * 128 + c) * 4];
    float acc = 0.f;
#pragma unroll
    for (int i = 0; i < 4; i++) {
        int tt = t - 3 + i;
        if (tt >= 0)
            acc = fmaf(in[(size_t)(m - 3 + i) * 2048 + col], wp[i], acc);
    }
    acc = acc / (1.f + expf(-acc));
    if (doNorm) {
        float ss = acc * acc;
#pragma unroll
        for (int mask = 16; mask > 0; mask >>= 1)
            ss += __shfl_xor_sync(0xffffffffu, ss, mask);
        __shared__ float sred[4];
        if ((threadIdx.x & 31) == 0) sred[threadIdx.x >> 5] = ss;
        __syncthreads();
        float tot = sred[0] + sred[1] + sred[2] + sred[3];
        float nrm = sqrtf(tot);
        acc = acc / fmaxf(nrm, 1e-12f);
    }
    out[(size_t)m * 2048 + col] = acc;
}

// ---------------- KDA delta-rule scan (128 thr, f32x2, short dot chains) ----------------
#define SCH 16
__global__ __launch_bounds__(128) void scan_kernel(const float* __restrict__ Qc,
                                                   const float* __restrict__ Kc,
                                                   const float* __restrict__ Vc,
                                                   const float* __restrict__ EG,
                                                   const float* __restrict__ Beta,
                                                   float* __restrict__ Y)
{
    const int chunkV = blockIdx.x & 3;
    const int bh = blockIdx.x >> 2;
    const int b = bh >> 4, h = bh & 15;
    const int tid = threadIdx.x;
    const int p = tid & 3;
    const int jj = tid >> 2;
    const int col = h * 128 + chunkV * 32 + jj;

    __shared__ float sk[SCH][144];
    __shared__ float sq[SCH][144];
    __shared__ float se[SCH][144];
    __shared__ float sv[SCH][32];
    __shared__ float sb[SCH];

    uint64_t S2[16];
#pragma unroll
    for (int r = 0; r < 16; r++) S2[r] = 0ull;

    const int pos = tid + ((tid >> 5) << 2);
    const int pbase = p * 36;

    for (int t0 = 0; t0 < TT; t0 += SCH) {
        __syncthreads();
#pragma unroll 4
        for (int s = 0; s < SCH; s++) {
            size_t off = (size_t)(b * TT + t0 + s) * 2048 + h * 128 + tid;
            sk[s][pos] = Kc[off];
            sq[s][pos] = Qc[off];
            se[s][pos] = EG[off];
        }
        if (tid < 32) {
#pragma unroll 4
            for (int s = 0; s < SCH; s++)
                sv[s][tid] = Vc[(size_t)(b * TT + t0 + s) * 2048 + h * 128 + chunkV * 32 + tid];
        }
        if (tid < SCH)
            sb[tid] = Beta[(size_t)(b * TT + t0 + tid) * HH + h];
        __syncthreads();

        for (int s = 0; s < SCH; s++) {
            const float* kp = &sk[s][pbase];
            const float* ep = &se[s][pbase];
            const float* qp = &sq[s][pbase];
            uint64_t k2[16];
            uint64_t d0 = 0ull, d1 = 0ull, d2 = 0ull, d3 = 0ull;
#pragma unroll
            for (int i = 0; i < 8; i++) {
                ulonglong2 kk = *(const ulonglong2*)(kp + 4 * i);
                ulonglong2 ee = *(const ulonglong2*)(ep + 4 * i);
                k2[2 * i] = kk.x; k2[2 * i + 1] = kk.y;
                uint64_t s0, s1;
                MUL2(s0, S2[2 * i],     ee.x);
                MUL2(s1, S2[2 * i + 1], ee.y);
                S2[2 * i] = s0; S2[2 * i + 1] = s1;
                if (i & 1) { FMA2(d2, kk.x, s0); FMA2(d3, kk.y, s1); }
                else       { FMA2(d0, kk.x, s0); FMA2(d1, kk.y, s1); }
            }
            float2 a0 = unpack2(d0), a1 = unpack2(d1), a2 = unpack2(d2), a3 = unpack2(d3);
            float dot = ((a0.x + a0.y) + (a1.x + a1.y)) + ((a2.x + a2.y) + (a3.x + a3.y));
            dot += __shfl_xor_sync(0xffffffffu, dot, 1);
            dot += __shfl_xor_sync(0xffffffffu, dot, 2);
            float u = sb[s] * (sv[s][jj] - dot);
            uint64_t u2 = pack2(u, u);
            uint64_t oa = 0ull, ob = 0ull;
#pragma unroll
            for (int i = 0; i < 8; i++) {
                ulonglong2 qq = *(const ulonglong2*)(qp + 4 * i);
                FMA2(S2[2 * i],     k2[2 * i],     u2);
                FMA2(S2[2 * i + 1], k2[2 * i + 1], u2);
                FMA2(oa, qq.x, S2[2 * i]);
                FMA2(ob, qq.y, S2[2 * i + 1]);
            }
            float2 ov = unpack2(oa), ow = unpack2(ob);
            float od = (ov.x + ov.y) + (ow.x + ow.y);
            od += __shfl_xor_sync(0xffffffffu, od, 1);
            od += __shfl_xor_sync(0xffffffffu, od, 2);
            if (p == 0)
                Y[(size_t)(b * TT + t0 + s) * 2048 + col] = od;
        }
    }
}

// ---------------- RMS norm + gate, emit bf16 hi/lo split ----------------
__global__ __launch_bounds__(128) void rmsgate_kernel(const float* __restrict__ Y,
                                                      const float* __restrict__ Gate,
                                                      const float* __restrict__ bg,
                                                      const float* __restrict__ onw,
                                                      __nv_bfloat16* __restrict__ Yh,
                                                      __nv_bfloat16* __restrict__ Yl)
{
    const int m = blockIdx.x >> 4;
    const int h = blockIdx.x & 15;
    const int c = threadIdx.x;
    const int col = h * 128 + c;
    float y = Y[(size_t)m * 2048 + col];
    float ss = y * y;
#pragma unroll
    for (int mask = 16; mask > 0; mask >>= 1)
        ss += __shfl_xor_sync(0xffffffffu, ss, mask);
    __shared__ float sred[4];
    if ((threadIdx.x & 31) == 0) sred[threadIdx.x >> 5] = ss;
    __syncthreads();
    float tot = sred[0] + sred[1] + sred[2] + sred[3];
    float r = rsqrtf(tot * (1.f / 128.f) + 1.1920929e-07f);
    float g = Gate[(size_t)m * 2048 + col] + bg[col];
    float v = y * r * onw[c] / (1.f + expf(-g));
    __nv_bfloat16 vh = __float2bfloat16(v);
    Yh[(size_t)m * 2048 + col] = vh;
    Yl[(size_t)m * 2048 + col] = __float2bfloat16(v - __bfloat162float(vh));
}

// ---------------- host ----------------
extern "C" void kernel_launch(void* const* d_in, const int* in_sizes, int n_in,
                              void* d_out, int out_size)
{
    const float* x     = (const float*)d_in[0];
    const float* Wq    = (const float*)d_in[1];
    const float* Wk    = (const float*)d_in[2];
    const float* Wv    = (const float*)d_in[3];
    const float* Wf1   = (const float*)d_in[4];
    const float* Wf2   = (const float*)d_in[5];
    const float* Wb    = (const float*)d_in[6];
    const float* Wg1   = (const float*)d_in[7];
    const float* Wg2   = (const float*)d_in[8];
    const float* bg    = (const float*)d_in[9];
    const float* onw   = (const float*)d_in[10];
    const float* Wout  = (const float*)d_in[11];
    const float* A_log = (const float*)d_in[12];
    const float* dtb   = (const float*)d_in[13];
    const float* qcw   = (const float*)d_in[14];
    const float* kcw   = (const float*)d_in[15];
    const float* vcw   = (const float*)d_in[16];
    float* out = (float*)d_out;

    float *Q, *K, *V, *Qc, *Kc, *Vc, *EG, *Gate, *Beta, *Y;
    cudaGetSymbolAddress((void**)&Q,   g_Q);
    cudaGetSymbolAddress((void**)&K,   g_K);
    cudaGetSymbolAddress((void**)&V,   g_V);
    cudaGetSymbolAddress((void**)&Qc,  g_Qc);
    cudaGetSymbolAddress((void**)&Kc,  g_Kc);
    cudaGetSymbolAddress((void**)&Vc,  g_Vc);
    cudaGetSymbolAddress((void**)&EG,  g_EG);
    cudaGetSymbolAddress((void**)&Gate,g_Gate);
    cudaGetSymbolAddress((void**)&Beta,g_Beta);
    cudaGetSymbolAddress((void**)&Y,   g_Y);

    __nv_bfloat16 *xh,*xl,*Yh,*Yl,*F1h,*F1l,*G1h,*G1l;
    __nv_bfloat16 *Wqh,*Wql,*Wkh,*Wkl,*Wvh,*Wvl,*Woh,*Wol;
    __nv_bfloat16 *Wf1h,*Wf1l,*Wg1h,*Wg1l,*Wf2h,*Wf2l,*Wg2h,*Wg2l;
    cudaGetSymbolAddress((void**)&xh, g_xh);   cudaGetSymbolAddress((void**)&xl, g_xl);
    cudaGetSymbolAddress((void**)&Yh, g_Yh);   cudaGetSymbolAddress((void**)&Yl, g_Yl);
    cudaGetSymbolAddress((void**)&F1h, g_F1h); cudaGetSymbolAddress((void**)&F1l, g_F1l);
    cudaGetSymbolAddress((void**)&G1h, g_G1h); cudaGetSymbolAddress((void**)&G1l, g_G1l);
    cudaGetSymbolAddress((void**)&Wqh, g_Wqh); cudaGetSymbolAddress((void**)&Wql, g_Wql);
    cudaGetSymbolAddress((void**)&Wkh, g_Wkh); cudaGetSymbolAddress((void**)&Wkl, g_Wkl);
    cudaGetSymbolAddress((void**)&Wvh, g_Wvh); cudaGetSymbolAddress((void**)&Wvl, g_Wvl);
    cudaGetSymbolAddress((void**)&Woh, g_Woh); cudaGetSymbolAddress((void**)&Wol, g_Wol);
    cudaGetSymbolAddress((void**)&Wf1h, g_Wf1h); cudaGetSymbolAddress((void**)&Wf1l, g_Wf1l);
    cudaGetSymbolAddress((void**)&Wg1h, g_Wg1h); cudaGetSymbolAddress((void**)&Wg1l, g_Wg1l);
    cudaGetSymbolAddress((void**)&Wf2h, g_Wf2h); cudaGetSymbolAddress((void**)&Wf2l, g_Wf2l);
    cudaGetSymbolAddress((void**)&Wg2h, g_Wg2h); cudaGetSymbolAddress((void**)&Wg2l, g_Wg2l);

    const int SMEM4 = 3 * (2 * 128 * 128 + 2 * 128 * 128);   // 196608 (NT=4)
    const int SMEM2 = 3 * (2 * 128 * 128 + 2 * 64 * 128);    // 147456 (NT=2)
    cudaFuncSetAttribute(mmagemmA<4>, cudaFuncAttributeMaxDynamicSharedMemorySize, SMEM4);
    cudaFuncSetAttribute(mmagemmA<2>, cudaFuncAttributeMaxDynamicSharedMemorySize, SMEM2);
    cudaFuncSetAttribute(mmagemmB<4>, cudaFuncAttributeMaxDynamicSharedMemorySize, SMEM4);

    // launch #1: all fp32->bf16 splits, one segmented kernel
    {
        SplitArgs sa{};
        const float* srcs[9] = {x, Wq, Wk, Wv, Wout, Wf1, Wg1, Wf2, Wg2};
        __nv_bfloat16* hs[9] = {xh, Wqh, Wkh, Wvh, Woh, Wf1h, Wg1h, Wf2h, Wg2h};
        __nv_bfloat16* ls[9] = {xl, Wql, Wkl, Wvl, Wol, Wf1l, Wg1l, Wf2l, Wg2l};
        const int elems[9] = {BT*DD, HK*DD, HK*DD, HV*DD, DD*HV, VD*DD, VD*DD, HK*VD, HV*VD};
        int cum = 0;
        for (int i = 0; i < 9; i++) {
            sa.src[i] = (const float4*)srcs[i];
            sa.h[i] = (__nv_bfloat162*)hs[i];
            sa.l[i] = (__nv_bfloat162*)ls[i];
            cum += elems[i] / 1024;
            sa.end[i] = cum;
        }
        splitall_kernel<<<cum, 256>>>(sa);
    }

    // launch #2: batched QKV projection (K=2048 -> 256-thread variant)
    {
        BatchArgs a{};
        for (int z = 0; z < 3; z++) { a.Ah[z] = xh; a.Al[z] = xl; a.mode[z] = 0; }
        a.Bh[0] = Wqh; a.Bl[0] = Wql; a.C[0] = Q;
        a.Bh[1] = Wkh; a.Bl[1] = Wkl; a.C[1] = K;
        a.Bh[2] = Wvh; a.Bl[2] = Wvl; a.C[2] = V;
        a.N = HK; a.Kd = DD;
        mmagemmA<4><<<dim3(HK / 128, BT / 128, 3), 256, SMEM4>>>(a);
    }

    // launch #3: batched F1/G1 (K=2048 -> 256-thread variant)
    {
        BatchArgs a{};
        for (int z = 0; z < 2; z++) { a.Ah[z] = xh; a.Al[z] = xl; a.mode[z] = 1; }
        a.Bh[0] = Wf1h; a.Bl[0] = Wf1l; a.Ch[0] = F1h; a.Cl[0] = F1l;
        a.Bh[1] = Wg1h; a.Bl[1] = Wg1l; a.Ch[1] = G1h; a.Cl[1] = G1l;
        a.N = VD; a.Kd = DD;
        mmagemmA<2><<<dim3(VD / 64, BT / 128, 2), 256, SMEM2>>>(a);
    }

    // launch #4: batched EG (decay fused) + Gate (K=128 -> 512-thread variant)
    {
        BatchArgs a{};
        a.Ah[0] = F1h; a.Al[0] = F1l; a.Bh[0] = Wf2h; a.Bl[0] = Wf2l; a.C[0] = EG;   a.mode[0] = 2;
        a.Ah[1] = G1h; a.Al[1] = G1l; a.Bh[1] = Wg2h; a.Bl[1] = Wg2l; a.C[1] = Gate; a.mode[1] = 0;
        a.A_log = A_log; a.dtb = dtb;
        a.N = HK; a.Kd = VD;
        mmagemmB<4><<<dim3(HK / 128, BT / 128, 2), 512, SMEM4>>>(a);
    }

    beta_kernel<<<BT / 8, 256>>>(x, Wb, Beta);

    convnorm_kernel<<<BT * HH, 128>>>(Q, qcw, Qc, 1);
    convnorm_kernel<<<BT * HH, 128>>>(K, kcw, Kc, 1);
    convnorm_kernel<<<BT * HH, 128>>>(V, vcw, Vc, 0);

    scan_kernel<<<BB * HH * 4, 128>>>(Qc, Kc, Vc, EG, Beta, Y);

    rmsgate_kernel<<<BT * HH, 128>>>(Y, Gate, bg, onw, Yh, Yl);

    // out projection (K=2048 -> 256-thread variant)
    {
        BatchArgs a{};
        a.Ah[0] = Yh; a.Al[0] = Yl; a.Bh[0] = Woh; a.Bl[0] = Wol; a.C[0] = out; a.mode[0] = 0;
        a.N = DD; a.Kd = HV;
        mmagemmA<4><<<dim3(DD / 128, BT / 128, 1), 256, SMEM4>>>(a);
    }
}

// round 14
// speedup vs baseline: 1.6132x; 1.6132x over previous
#include <cuda_runtime.h>
#include <cuda_bf16.h>
#include <math.h>
#include <stdint.h>

// Problem constants
#define BB 2
#define TT 2048
#define DD 2048
#define HH 16
#define KD 128
#define VD 128
#define BT (BB*TT)          // 4096
#define HK (HH*KD)          // 2048
#define HV (HH*VD)          // 2048

// ---------------- scratch ----------------
__device__ float g_Q[BT*HK];
__device__ float g_K[BT*HK];
__device__ float g_V[BT*HV];
__device__ float g_Qc[BT*HK];
__device__ float g_Kc[BT*HK];
__device__ float g_Vc[BT*HV];
__device__ float g_EG[BT*HK];
__device__ float g_Gate[BT*HV];
__device__ float g_Beta[BT*HH];
__device__ float g_Y[BT*HV];

__device__ __nv_bfloat16 g_xh[BT*DD],  g_xl[BT*DD];
__device__ __nv_bfloat16 g_Yh[BT*HV],  g_Yl[BT*HV];
__device__ __nv_bfloat16 g_F1h[BT*VD], g_F1l[BT*VD];
__device__ __nv_bfloat16 g_G1h[BT*VD], g_G1l[BT*VD];
__device__ __nv_bfloat16 g_Wqh[HK*DD], g_Wql[HK*DD];
__device__ __nv_bfloat16 g_Wkh[HK*DD], g_Wkl[HK*DD];
__device__ __nv_bfloat16 g_Wvh[HV*DD], g_Wvl[HV*DD];
__device__ __nv_bfloat16 g_Woh[DD*HV], g_Wol[DD*HV];
__device__ __nv_bfloat16 g_Wf1h[VD*DD], g_Wf1l[VD*DD];
__device__ __nv_bfloat16 g_Wg1h[VD*DD], g_Wg1l[VD*DD];
__device__ __nv_bfloat16 g_Wf2h[HK*VD], g_Wf2l[HK*VD];
__device__ __nv_bfloat16 g_Wg2h[HV*VD], g_Wg2l[HV*VD];

// ================= helpers =================
#define SWZ(off) ((off) ^ (((off) >> 3) & 0x70))

__device__ __forceinline__ uint32_t sm2u(const void* p) {
    uint32_t a;
    asm("{ .reg .u64 t; cvta.to.shared.u64 t, %1; cvt.u32.u64 %0, t; }" : "=r"(a) : "l"(p));
    return a;
}

#define CP_ASYNC16(dst, src) \
    asm volatile("cp.async.cg.shared.global [%0], [%1], 16;" :: "r"(dst), "l"(src))
#define CP_COMMIT() asm volatile("cp.async.commit_group;")
#define CP_WAIT1()  asm volatile("cp.async.wait_group 1;")
#define CP_WAIT0()  asm volatile("cp.async.wait_group 0;")

#define LDMAT4(r0, r1, r2, r3, addr) \
    asm volatile("ldmatrix.sync.aligned.m8n8.x4.shared.b16 {%0,%1,%2,%3}, [%4];" \
        : "=r"(r0), "=r"(r1), "=r"(r2), "=r"(r3) : "r"(addr))

#define MMA_BF16(d, a, b) \
    asm volatile("mma.sync.aligned.m16n8k16.row.col.f32.bf16.bf16.f32 " \
        "{%0,%1,%2,%3},{%4,%5,%6,%7},{%8,%9},{%0,%1,%2,%3};" \
        : "+f"((d)[0]), "+f"((d)[1]), "+f"((d)[2]), "+f"((d)[3]) \
        : "r"((a)[0]), "r"((a)[1]), "r"((a)[2]), "r"((a)[3]), "r"((b)[0]), "r"((b)[1]))

// packed f32x2 ops
#define FMA2(d, a, b) asm("fma.rn.f32x2 %0, %1, %2, %0;" : "+l"(d) : "l"(a), "l"(b))
#define MUL2(d, a, b) asm("mul.rn.f32x2 %0, %1, %2;" : "=l"(d) : "l"(a), "l"(b))

__device__ __forceinline__ uint64_t pack2(float x, float y) {
    uint64_t r; asm("mov.b64 %0, {%1, %2};" : "=l"(r) : "f"(x), "f"(y)); return r;
}
__device__ __forceinline__ float2 unpack2(uint64_t v) {
    float x, y; asm("mov.b64 {%0, %1}, %2;" : "=f"(x), "=f"(y) : "l"(v));
    return make_float2(x, y);
}

struct BatchArgs {
    const __nv_bfloat16* Ah[3];
    const __nv_bfloat16* Al[3];
    const __nv_bfloat16* Bh[3];
    const __nv_bfloat16* Bl[3];
    float* C[3];
    __nv_bfloat16* Ch[3];
    __nv_bfloat16* Cl[3];
    int mode[3];
    const float* A_log;
    const float* dtb;
    int N, Kd;
};

// fully-unrolled epilogue (MT compile-time -> accumulators stay in registers)
template<int MT, int NT>
__device__ __forceinline__ void gemm_epilogue(const BatchArgs& args, int z,
                                              float acc[MT][NT][4],
                                              int m0, int n0, int mrowbase,
                                              int nw, int lane, int N)
{
    float* __restrict__ C = args.C[z];
    __nv_bfloat16* __restrict__ Ch = args.Ch[z];
    __nv_bfloat16* __restrict__ Cl = args.Cl[z];
    const int mode = args.mode[z];
#pragma unroll
    for (int mt = 0; mt < MT; mt++)
#pragma unroll
        for (int nt = 0; nt < NT; nt++) {
            int r = m0 + mrowbase + mt * 16 + (lane >> 2);
            int c = n0 + nw * NT * 8 + nt * 8 + (lane & 3) * 2;
#pragma unroll
            for (int half = 0; half < 2; half++) {
                int rr = r + half * 8;
                float v0 = acc[mt][nt][half * 2 + 0];
                float v1 = acc[mt][nt][half * 2 + 1];
                size_t off = (size_t)rr * N + c;
                if (mode == 0) {
                    *(float2*)&C[off] = make_float2(v0, v1);
                } else if (mode == 1) {
                    __nv_bfloat16 h0 = __float2bfloat16(v0);
                    __nv_bfloat16 h1 = __float2bfloat16(v1);
                    __nv_bfloat162 hh; hh.x = h0; hh.y = h1;
                    __nv_bfloat162 ll;
                    ll.x = __float2bfloat16(v0 - __bfloat162float(h0));
                    ll.y = __float2bfloat16(v1 - __bfloat162float(h1));
                    *(__nv_bfloat162*)&Ch[off] = hh;
                    *(__nv_bfloat162*)&Cl[off] = ll;
                } else {
                    int h = c >> 7;
                    float ea = expf(args.A_log[h]);
                    float x0 = v0 + args.dtb[c], x1 = v1 + args.dtb[c + 1];
                    float sp0 = (x0 > 20.f) ? x0 : log1pf(expf(x0));
                    float sp1 = (x1 > 20.f) ? x1 : log1pf(expf(x1));
                    *(float2*)&C[off] = make_float2(expf(-ea * sp0), expf(-ea * sp1));
                }
            }
        }
}

// ===== 256-thread variant (8 warps 2x4, mt=4, 3-stage) — best for K=2048 =====
template<int NT>
__global__ __launch_bounds__(256, 1) void mmagemmA(const BatchArgs args)
{
    constexpr int BN  = NT * 32;
    constexpr int WN  = NT * 8;
    constexpr int ASZ = 128 * 128;
    constexpr int BSZ = BN * 128;
    constexpr int STG = 2 * ASZ + 2 * BSZ;
    extern __shared__ __align__(1024) char smem[];
    const uint32_t sb = sm2u(smem);
    const int tid = threadIdx.x;
    const int z = blockIdx.z;
    const int m0 = blockIdx.y * 128, n0 = blockIdx.x * BN;
    const int N = args.N, Kd = args.Kd;

    const __nv_bfloat16* __restrict__ Ah = args.Ah[z];
    const __nv_bfloat16* __restrict__ Al = args.Al[z];
    const __nv_bfloat16* __restrict__ Bh = args.Bh[z];
    const __nv_bfloat16* __restrict__ Bl = args.Bl[z];

    auto prefetch = [&](int stg, int k0) {
        uint32_t b = sb + stg * STG;
        for (int idx = tid; idx < 1024; idx += 256) {
            int row = idx >> 3, ck = idx & 7;
            size_t go = ((size_t)(m0 + row) * Kd + k0) * 2 + ck * 16;
            uint32_t so = b + SWZ(row * 128 + ck * 16);
            CP_ASYNC16(so,       (const char*)Ah + go);
            CP_ASYNC16(so + ASZ, (const char*)Al + go);
        }
        for (int idx = tid; idx < BN * 8; idx += 256) {
            int row = idx >> 3, ck = idx & 7;
            size_t go = ((size_t)(n0 + row) * Kd + k0) * 2 + ck * 16;
            uint32_t so = b + 2 * ASZ + SWZ(row * 128 + ck * 16);
            CP_ASYNC16(so,       (const char*)Bh + go);
            CP_ASYNC16(so + BSZ, (const char*)Bl + go);
        }
    };

    const int wid = tid >> 5, lane = tid & 31;
    const int mw = wid >> 2, nw = wid & 3;
    const uint32_t xm = (lane & 7) * 16;
    const int arow = mw * 64 + (lane & 15);
    const int asel = ((lane >> 4) & 1) << 4;
    const int brow = nw * WN + (lane & 7) + (((lane >> 4) & 1) << 3);
    const int bsel = ((lane >> 3) & 1) << 4;

    float acc[4][NT][4];
#pragma unroll
    for (int mt = 0; mt < 4; mt++)
#pragma unroll
        for (int nt = 0; nt < NT; nt++)
#pragma unroll
            for (int q = 0; q < 4; q++) acc[mt][nt][q] = 0.f;

    const int iters = Kd >> 6;
    prefetch(0, 0);
    CP_COMMIT();
    if (iters > 1) { prefetch(1, 64); }
    CP_COMMIT();
    CP_WAIT1();
    __syncthreads();

    int stg = 0;
    for (int it = 0; it < iters; it++) {
        if (it + 2 < iters) {
            int ns = stg + 2; if (ns >= 3) ns -= 3;
            prefetch(ns, (it + 2) * 64);
            CP_COMMIT();
        }

        const uint32_t b = sb + stg * STG;
#pragma unroll
        for (int kk = 0; kk < 4; kk++) {
            const int koff = kk * 32;
            uint32_t ah[4][4], al[4][4];
#pragma unroll
            for (int mt = 0; mt < 4; mt++) {
                uint32_t ad = b + (uint32_t)(arow + mt * 16) * 128 + ((koff + asel) ^ xm);
                LDMAT4(ah[mt][0], ah[mt][1], ah[mt][2], ah[mt][3], ad);
                LDMAT4(al[mt][0], al[mt][1], al[mt][2], al[mt][3], ad + ASZ);
            }
            uint32_t bh[NT][2], bl[NT][2];
#pragma unroll
            for (int j = 0; j < NT / 2; j++) {
                uint32_t bd = b + 2 * ASZ + (uint32_t)(brow + j * 16) * 128 + ((koff + bsel) ^ xm);
                LDMAT4(bh[2*j][0], bh[2*j][1], bh[2*j+1][0], bh[2*j+1][1], bd);
                LDMAT4(bl[2*j][0], bl[2*j][1], bl[2*j+1][0], bl[2*j+1][1], bd + BSZ);
            }
#pragma unroll
            for (int mt = 0; mt < 4; mt++)
#pragma unroll
                for (int nt = 0; nt < NT; nt++) {
                    MMA_BF16(acc[mt][nt], ah[mt], bh[nt]);
                    MMA_BF16(acc[mt][nt], ah[mt], bl[nt]);
                    MMA_BF16(acc[mt][nt], al[mt], bh[nt]);
                }
        }

        if (it + 1 < iters) { CP_WAIT1(); }
        __syncthreads();
        stg++; if (stg == 3) stg = 0;
    }

    gemm_epilogue<4, NT>(args, z, acc, m0, n0, mw * 64, nw, lane, N);
}

// ===== 512-thread variant (16 warps 4x4, mt=2, 3-stage) — best for K=128 =====
template<int NT>
__global__ __launch_bounds__(512, 1) void mmagemmB(const BatchArgs args)
{
    constexpr int BN  = NT * 32;
    constexpr int WN  = NT * 8;
    constexpr int ASZ = 128 * 128;
    constexpr int BSZ = BN * 128;
    constexpr int STG = 2 * ASZ + 2 * BSZ;
    extern __shared__ __align__(1024) char smem[];
    const uint32_t sb = sm2u(smem);
    const int tid = threadIdx.x;
    const int z = blockIdx.z;
    const int m0 = blockIdx.y * 128, n0 = blockIdx.x * BN;
    const int N = args.N, Kd = args.Kd;

    const __nv_bfloat16* __restrict__ Ah = args.Ah[z];
    const __nv_bfloat16* __restrict__ Al = args.Al[z];
    const __nv_bfloat16* __restrict__ Bh = args.Bh[z];
    const __nv_bfloat16* __restrict__ Bl = args.Bl[z];

    auto prefetch = [&](int stg, int k0) {
        uint32_t b = sb + stg * STG;
#pragma unroll
        for (int idx = tid; idx < 1024; idx += 512) {
            int row = idx >> 3, ck = idx & 7;
            size_t go = ((size_t)(m0 + row) * Kd + k0) * 2 + ck * 16;
            uint32_t so = b + SWZ(row * 128 + ck * 16);
            CP_ASYNC16(so,       (const char*)Ah + go);
            CP_ASYNC16(so + ASZ, (const char*)Al + go);
        }
        for (int idx = tid; idx < BN * 8; idx += 512) {
            int row = idx >> 3, ck = idx & 7;
            size_t go = ((size_t)(n0 + row) * Kd + k0) * 2 + ck * 16;
            uint32_t so = b + 2 * ASZ + SWZ(row * 128 + ck * 16);
            CP_ASYNC16(so,       (const char*)Bh + go);
            CP_ASYNC16(so + BSZ, (const char*)Bl + go);
        }
    };

    const int wid = tid >> 5, lane = tid & 31;
    const int mw = wid >> 2, nw = wid & 3;
    const uint32_t xm = (lane & 7) * 16;
    const int arow = mw * 32 + (lane & 15);
    const int asel = ((lane >> 4) & 1) << 4;
    const int brow = nw * WN + (lane & 7) + (((lane >> 4) & 1) << 3);
    const int bsel = ((lane >> 3) & 1) << 4;

    float acc[2][NT][4];
#pragma unroll
    for (int mt = 0; mt < 2; mt++)
#pragma unroll
        for (int nt = 0; nt < NT; nt++)
#pragma unroll
            for (int q = 0; q < 4; q++) acc[mt][nt][q] = 0.f;

    const int iters = Kd >> 6;
    prefetch(0, 0);
    CP_COMMIT();
    if (iters > 1) { prefetch(1, 64); }
    CP_COMMIT();
    CP_WAIT1();
    __syncthreads();

    int stg = 0;
    for (int it = 0; it < iters; it++) {
        if (it + 2 < iters) {
            int ns = stg + 2; if (ns >= 3) ns -= 3;
            prefetch(ns, (it + 2) * 64);
            CP_COMMIT();
        }

        const uint32_t b = sb + stg * STG;
#pragma unroll
        for (int kk = 0; kk < 4; kk++) {
            const int koff = kk * 32;
            uint32_t ah[2][4], al[2][4];
#pragma unroll
            for (int mt = 0; mt < 2; mt++) {
                uint32_t ad = b + (uint32_t)(arow + mt * 16) * 128 + ((koff + asel) ^ xm);
                LDMAT4(ah[mt][0], ah[mt][1], ah[mt][2], ah[mt][3], ad);
                LDMAT4(al[mt][0], al[mt][1], al[mt][2], al[mt][3], ad + ASZ);
            }
            uint32_t bh[NT][2], bl[NT][2];
#pragma unroll
            for (int j = 0; j < NT / 2; j++) {
                uint32_t bd = b + 2 * ASZ + (uint32_t)(brow + j * 16) * 128 + ((koff + bsel) ^ xm);
                LDMAT4(bh[2*j][0], bh[2*j][1], bh[2*j+1][0], bh[2*j+1][1], bd);
                LDMAT4(bl[2*j][0], bl[2*j][1], bl[2*j+1][0], bl[2*j+1][1], bd + BSZ);
            }
#pragma unroll
            for (int mt = 0; mt < 2; mt++)
#pragma unroll
                for (int nt = 0; nt < NT; nt++) {
                    MMA_BF16(acc[mt][nt], ah[mt], bh[nt]);
                    MMA_BF16(acc[mt][nt], ah[mt], bl[nt]);
                    MMA_BF16(acc[mt][nt], al[mt], bh[nt]);
                }
        }

        if (it + 1 < iters) { CP_WAIT1(); }
        __syncthreads();
        stg++; if (stg == 3) stg = 0;
    }

    gemm_epilogue<2, NT>(args, z, acc, m0, n0, mw * 32, nw, lane, N);
}

// ---------------- fused segmented split ----------------
struct SplitArgs {
    const float4* src[9];
    __nv_bfloat162* h[9];
    __nv_bfloat162* l[9];
    int end[9];
};

__global__ void splitall_kernel(const SplitArgs a)
{
    int bid = blockIdx.x;
    int seg = 0;
#pragma unroll
    for (int i = 0; i < 8; i++)
        if (bid >= a.end[i]) seg = i + 1;
    int start = (seg == 0) ? 0 : a.end[seg - 1];
    int i4 = (bid - start) * 256 + threadIdx.x;
    float4 v = a.src[seg][i4];
    __nv_bfloat16 hx = __float2bfloat16(v.x), hy = __float2bfloat16(v.y);
    __nv_bfloat16 hz = __float2bfloat16(v.z), hw = __float2bfloat16(v.w);
    __nv_bfloat162 p0, p1, q0, q1;
    p0.x = hx; p0.y = hy; p1.x = hz; p1.y = hw;
    q0.x = __float2bfloat16(v.x - __bfloat162float(hx));
    q0.y = __float2bfloat16(v.y - __bfloat162float(hy));
    q1.x = __float2bfloat16(v.z - __bfloat162float(hz));
    q1.y = __float2bfloat16(v.w - __bfloat162float(hw));
    a.h[seg][i4 * 2] = p0; a.h[seg][i4 * 2 + 1] = p1;
    a.l[seg][i4 * 2] = q0; a.l[seg][i4 * 2 + 1] = q1;
}

// ---------------- beta = sigmoid(x @ Wb^T), 8 rows per block (Wb L1 reuse) ----------------
__global__ __launch_bounds__(256) void beta_kernel(const float* __restrict__ x,
                                                   const float* __restrict__ Wb,
                                                   float* __restrict__ Beta)
{
    const int tid = threadIdx.x;
    const int warp = tid >> 5, lane = tid & 31;
    __shared__ float red[HH][9];

    for (int r = 0; r < 8; r++) {
        const int m = blockIdx.x * 8 + r;
        if (r > 0) __syncthreads();
        float acc[HH];
#pragma unroll
        for (int h = 0; h < HH; h++) acc[h] = 0.f;
        for (int d = tid; d < DD; d += 256) {
            float xv = x[(size_t)m * DD + d];
#pragma unroll
            for (int h = 0; h < HH; h++)
                acc[h] = fmaf(xv, Wb[(size_t)h * DD + d], acc[h]);
        }
#pragma unroll
        for (int h = 0; h < HH; h++) {
            float v = acc[h];
#pragma unroll
            for (int mask = 16; mask > 0; mask >>= 1)
                v += __shfl_xor_sync(0xffffffffu, v, mask);
            if (lane == 0) red[h][warp] = v;
        }
        __syncthreads();
        if (tid < HH) {
            float s = 0.f;
#pragma unroll
            for (int w = 0; w < 8; w++) s += red[tid][w];
            Beta[(size_t)m * HH + tid] = 1.f / (1.f + expf(-s));
        }
    }
}

// ---------------- causal depthwise conv (k=4) + silu (+ optional l2norm) ----------------
__global__ __launch_bounds__(128) void convnorm_kernel(const float* __restrict__ in,
                                                       const float* __restrict__ w,
                                                       float* __restrict__ out,
                                                       int doNorm)
{
    const int m = blockIdx.x >> 4;
    const int h = blockIdx.x & 15;
    const int t = m & (TT - 1);
    const int c = threadIdx.x;
    const int col = h * 128 + c;
    const float* wp = &w[(size_t)(h * 128 + c) * 4];
    float acc = 0.f;
#pragma unroll
    for (int i = 0; i < 4; i++) {
        int tt = t - 3 + i;
        if (tt >= 0)
            acc = fmaf(in[(size_t)(m - 3 + i) * 2048 + col], wp[i], acc);
    }
    acc = acc / (1.f + expf(-acc));
    if (doNorm) {
        float ss = acc * acc;
#pragma unroll
        for (int mask = 16; mask > 0; mask >>= 1)
            ss += __shfl_xor_sync(0xffffffffu, ss, mask);
        __shared__ float sred[4];
        if ((threadIdx.x & 31) == 0) sred[threadIdx.x >> 5] = ss;
        __syncthreads();
        float tot = sred[0] + sred[1] + sred[2] + sred[3];
        float nrm = sqrtf(tot);
        acc = acc / fmaxf(nrm, 1e-12f);
    }
    out[(size_t)m * 2048 + col] = acc;
}

// ---------------- KDA delta-rule scan (128 thr, f32x2, short dot chains) ----------------
#define SCH 16
__global__ __launch_bounds__(128) void scan_kernel(const float* __restrict__ Qc,
                                                   const float* __restrict__ Kc,
                                                   const float* __restrict__ Vc,
                                                   const float* __restrict__ EG,
                                                   const float* __restrict__ Beta,
                                                   float* __restrict__ Y)
{
    const int chunkV = blockIdx.x & 3;
    const int bh = blockIdx.x >> 2;
    const int b = bh >> 4, h = bh & 15;
    const int tid = threadIdx.x;
    const int p = tid & 3;
    const int jj = tid >> 2;
    const int col = h * 128 + chunkV * 32 + jj;

    __shared__ float sk[SCH][144];
    __shared__ float sq[SCH][144];
    __shared__ float se[SCH][144];
    __shared__ float sv[SCH][32];
    __shared__ float sb[SCH];

    uint64_t S2[16];
#pragma unroll
    for (int r = 0; r < 16; r++) S2[r] = 0ull;

    const int pos = tid + ((tid >> 5) << 2);
    const int pbase = p * 36;

    for (int t0 = 0; t0 < TT; t0 += SCH) {
        __syncthreads();
#pragma unroll 4
        for (int s = 0; s < SCH; s++) {
            size_t off = (size_t)(b * TT + t0 + s) * 2048 + h * 128 + tid;
            sk[s][pos] = Kc[off];
            sq[s][pos] = Qc[off];
            se[s][pos] = EG[off];
        }
        if (tid < 32) {
#pragma unroll 4
            for (int s = 0; s < SCH; s++)
                sv[s][tid] = Vc[(size_t)(b * TT + t0 + s) * 2048 + h * 128 + chunkV * 32 + tid];
        }
        if (tid < SCH)
            sb[tid] = Beta[(size_t)(b * TT + t0 + tid) * HH + h];
        __syncthreads();

        for (int s = 0; s < SCH; s++) {
            const float* kp = &sk[s][pbase];
            const float* ep = &se[s][pbase];
            const float* qp = &sq[s][pbase];
            uint64_t k2[16];
            uint64_t d0 = 0ull, d1 = 0ull, d2 = 0ull, d3 = 0ull;
#pragma unroll
            for (int i = 0; i < 8; i++) {
                ulonglong2 kk = *(const ulonglong2*)(kp + 4 * i);
                ulonglong2 ee = *(const ulonglong2*)(ep + 4 * i);
                k2[2 * i] = kk.x; k2[2 * i + 1] = kk.y;
                uint64_t s0, s1;
                MUL2(s0, S2[2 * i],     ee.x);
                MUL2(s1, S2[2 * i + 1], ee.y);
                S2[2 * i] = s0; S2[2 * i + 1] = s1;
                if (i & 1) { FMA2(d2, kk.x, s0); FMA2(d3, kk.y, s1); }
                else       { FMA2(d0, kk.x, s0); FMA2(d1, kk.y, s1); }
            }
            float2 a0 = unpack2(d0), a1 = unpack2(d1), a2 = unpack2(d2), a3 = unpack2(d3);
            float dot = ((a0.x + a0.y) + (a1.x + a1.y)) + ((a2.x + a2.y) + (a3.x + a3.y));
            dot += __shfl_xor_sync(0xffffffffu, dot, 1);
            dot += __shfl_xor_sync(0xffffffffu, dot, 2);
            float u = sb[s] * (sv[s][jj] - dot);
            uint64_t u2 = pack2(u, u);
            uint64_t oa = 0ull, ob = 0ull;
#pragma unroll
            for (int i = 0; i < 8; i++) {
                ulonglong2 qq = *(const ulonglong2*)(qp + 4 * i);
                FMA2(S2[2 * i],     k2[2 * i],     u2);
                FMA2(S2[2 * i + 1], k2[2 * i + 1], u2);
                FMA2(oa, qq.x, S2[2 * i]);
                FMA2(ob, qq.y, S2[2 * i + 1]);
            }
            float2 ov = unpack2(oa), ow = unpack2(ob);
            float od = (ov.x + ov.y) + (ow.x + ow.y);
            od += __shfl_xor_sync(0xffffffffu, od, 1);
            od += __shfl_xor_sync(0xffffffffu, od, 2);
            if (p == 0)
                Y[(size_t)(b * TT + t0 + s) * 2048 + col] = od;
        }
    }
}

// ---------------- RMS norm + gate, emit bf16 hi/lo split ----------------
__global__ __launch_bounds__(128) void rmsgate_kernel(const float* __restrict__ Y,
                                                      const float* __restrict__ Gate,
                                                      const float* __restrict__ bg,
                                                      const float* __restrict__ onw,
                                                      __nv_bfloat16* __restrict__ Yh,
                                                      __nv_bfloat16* __restrict__ Yl)
{
    const int m = blockIdx.x >> 4;
    const int h = blockIdx.x & 15;
    const int c = threadIdx.x;
    const int col = h * 128 + c;
    float y = Y[(size_t)m * 2048 + col];
    float ss = y * y;
#pragma unroll
    for (int mask = 16; mask > 0; mask >>= 1)
        ss += __shfl_xor_sync(0xffffffffu, ss, mask);
    __shared__ float sred[4];
    if ((threadIdx.x & 31) == 0) sred[threadIdx.x >> 5] = ss;
    __syncthreads();
    float tot = sred[0] + sred[1] + sred[2] + sred[3];
    float r = rsqrtf(tot * (1.f / 128.f) + 1.1920929e-07f);
    float g = Gate[(size_t)m * 2048 + col] + bg[col];
    float v = y * r * onw[c] / (1.f + expf(-g));
    __nv_bfloat16 vh = __float2bfloat16(v);
    Yh[(size_t)m * 2048 + col] = vh;
    Yl[(size_t)m * 2048 + col] = __float2bfloat16(v - __bfloat162float(vh));
}

// ---------------- host ----------------
extern "C" void kernel_launch(void* const* d_in, const int* in_sizes, int n_in,
                              void* d_out, int out_size)
{
    const float* x     = (const float*)d_in[0];
    const float* Wq    = (const float*)d_in[1];
    const float* Wk    = (const float*)d_in[2];
    const float* Wv    = (const float*)d_in[3];
    const float* Wf1   = (const float*)d_in[4];
    const float* Wf2   = (const float*)d_in[5];
    const float* Wb    = (const float*)d_in[6];
    const float* Wg1   = (const float*)d_in[7];
    const float* Wg2   = (const float*)d_in[8];
    const float* bg    = (const float*)d_in[9];
    const float* onw   = (const float*)d_in[10];
    const float* Wout  = (const float*)d_in[11];
    const float* A_log = (const float*)d_in[12];
    const float* dtb   = (const float*)d_in[13];
    const float* qcw   = (const float*)d_in[14];
    const float* kcw   = (const float*)d_in[15];
    const float* vcw   = (const float*)d_in[16];
    float* out = (float*)d_out;

    float *Q, *K, *V, *Qc, *Kc, *Vc, *EG, *Gate, *Beta, *Y;
    cudaGetSymbolAddress((void**)&Q,   g_Q);
    cudaGetSymbolAddress((void**)&K,   g_K);
    cudaGetSymbolAddress((void**)&V,   g_V);
    cudaGetSymbolAddress((void**)&Qc,  g_Qc);
    cudaGetSymbolAddress((void**)&Kc,  g_Kc);
    cudaGetSymbolAddress((void**)&Vc,  g_Vc);
    cudaGetSymbolAddress((void**)&EG,  g_EG);
    cudaGetSymbolAddress((void**)&Gate,g_Gate);
    cudaGetSymbolAddress((void**)&Beta,g_Beta);
    cudaGetSymbolAddress((void**)&Y,   g_Y);

    __nv_bfloat16 *xh,*xl,*Yh,*Yl,*F1h,*F1l,*G1h,*G1l;
    __nv_bfloat16 *Wqh,*Wql,*Wkh,*Wkl,*Wvh,*Wvl,*Woh,*Wol;
    __nv_bfloat16 *Wf1h,*Wf1l,*Wg1h,*Wg1l,*Wf2h,*Wf2l,*Wg2h,*Wg2l;
    cudaGetSymbolAddress((void**)&xh, g_xh);   cudaGetSymbolAddress((void**)&xl, g_xl);
    cudaGetSymbolAddress((void**)&Yh, g_Yh);   cudaGetSymbolAddress((void**)&Yl, g_Yl);
    cudaGetSymbolAddress((void**)&F1h, g_F1h); cudaGetSymbolAddress((void**)&F1l, g_F1l);
    cudaGetSymbolAddress((void**)&G1h, g_G1h); cudaGetSymbolAddress((void**)&G1l, g_G1l);
    cudaGetSymbolAddress((void**)&Wqh, g_Wqh); cudaGetSymbolAddress((void**)&Wql, g_Wql);
    cudaGetSymbolAddress((void**)&Wkh, g_Wkh); cudaGetSymbolAddress((void**)&Wkl, g_Wkl);
    cudaGetSymbolAddress((void**)&Wvh, g_Wvh); cudaGetSymbolAddress((void**)&Wvl, g_Wvl);
    cudaGetSymbolAddress((void**)&Woh, g_Woh); cudaGetSymbolAddress((void**)&Wol, g_Wol);
    cudaGetSymbolAddress((void**)&Wf1h, g_Wf1h); cudaGetSymbolAddress((void**)&Wf1l, g_Wf1l);
    cudaGetSymbolAddress((void**)&Wg1h, g_Wg1h); cudaGetSymbolAddress((void**)&Wg1l, g_Wg1l);
    cudaGetSymbolAddress((void**)&Wf2h, g_Wf2h); cudaGetSymbolAddress((void**)&Wf2l, g_Wf2l);
    cudaGetSymbolAddress((void**)&Wg2h, g_Wg2h); cudaGetSymbolAddress((void**)&Wg2l, g_Wg2l);

    const int SMEM4 = 3 * (2 * 128 * 128 + 2 * 128 * 128);   // 196608 (NT=4)
    const int SMEM2 = 3 * (2 * 128 * 128 + 2 * 64 * 128);    // 147456 (NT=2)
    cudaFuncSetAttribute(mmagemmA<4>, cudaFuncAttributeMaxDynamicSharedMemorySize, SMEM4);
    cudaFuncSetAttribute(mmagemmA<2>, cudaFuncAttributeMaxDynamicSharedMemorySize, SMEM2);
    cudaFuncSetAttribute(mmagemmB<4>, cudaFuncAttributeMaxDynamicSharedMemorySize, SMEM4);

    // launch #1: all fp32->bf16 splits, one segmented kernel
    {
        SplitArgs sa{};
        const float* srcs[9] = {x, Wq, Wk, Wv, Wout, Wf1, Wg1, Wf2, Wg2};
        __nv_bfloat16* hs[9] = {xh, Wqh, Wkh, Wvh, Woh, Wf1h, Wg1h, Wf2h, Wg2h};
        __nv_bfloat16* ls[9] = {xl, Wql, Wkl, Wvl, Wol, Wf1l, Wg1l, Wf2l, Wg2l};
        const int elems[9] = {BT*DD, HK*DD, HK*DD, HV*DD, DD*HV, VD*DD, VD*DD, HK*VD, HV*VD};
        int cum = 0;
        for (int i = 0; i < 9; i++) {
            sa.src[i] = (const float4*)srcs[i];
            sa.h[i] = (__nv_bfloat162*)hs[i];
            sa.l[i] = (__nv_bfloat162*)ls[i];
            cum += elems[i] / 1024;
            sa.end[i] = cum;
        }
        splitall_kernel<<<cum, 256>>>(sa);
    }

    // launch #2: batched QKV projection (K=2048 -> 256-thread variant)
    {
        BatchArgs a{};
        for (int z = 0; z < 3; z++) { a.Ah[z] = xh; a.Al[z] = xl; a.mode[z] = 0; }
        a.Bh[0] = Wqh; a.Bl[0] = Wql; a.C[0] = Q;
        a.Bh[1] = Wkh; a.Bl[1] = Wkl; a.C[1] = K;
        a.Bh[2] = Wvh; a.Bl[2] = Wvl; a.C[2] = V;
        a.N = HK; a.Kd = DD;
        mmagemmA<4><<<dim3(HK / 128, BT / 128, 3), 256, SMEM4>>>(a);
    }

    // launch #3: batched F1/G1 (K=2048 -> 256-thread variant)
    {
        BatchArgs a{};
        for (int z = 0; z < 2; z++) { a.Ah[z] = xh; a.Al[z] = xl; a.mode[z] = 1; }
        a.Bh[0] = Wf1h; a.Bl[0] = Wf1l; a.Ch[0] = F1h; a.Cl[0] = F1l;
        a.Bh[1] = Wg1h; a.Bl[1] = Wg1l; a.Ch[1] = G1h; a.Cl[1] = G1l;
        a.N = VD; a.Kd = DD;
        mmagemmA<2><<<dim3(VD / 64, BT / 128, 2), 256, SMEM2>>>(a);
    }

    // launch #4: batched EG (decay fused) + Gate (K=128 -> 512-thread variant)
    {
        BatchArgs a{};
        a.Ah[0] = F1h; a.Al[0] = F1l; a.Bh[0] = Wf2h; a.Bl[0] = Wf2l; a.C[0] = EG;   a.mode[0] = 2;
        a.Ah[1] = G1h; a.Al[1] = G1l; a.Bh[1] = Wg2h; a.Bl[1] = Wg2l; a.C[1] = Gate; a.mode[1] = 0;
        a.A_log = A_log; a.dtb = dtb;
        a.N = HK; a.Kd = VD;
        mmagemmB<4><<<dim3(HK / 128, BT / 128, 2), 512, SMEM4>>>(a);
    }

    beta_kernel<<<BT / 8, 256>>>(x, Wb, Beta);

    convnorm_kernel<<<BT * HH, 128>>>(Q, qcw, Qc, 1);
    convnorm_kernel<<<BT * HH, 128>>>(K, kcw, Kc, 1);
    convnorm_kernel<<<BT * HH, 128>>>(V, vcw, Vc, 0);

    scan_kernel<<<BB * HH * 4, 128>>>(Qc, Kc, Vc, EG, Beta, Y);

    rmsgate_kernel<<<BT * HH, 128>>>(Y, Gate, bg, onw, Yh, Yl);

    // out projection (K=2048 -> 256-thread variant)
    {
        BatchArgs a{};
        a.Ah[0] = Yh; a.Al[0] = Yl; a.Bh[0] = Woh; a.Bl[0] = Wol; a.C[0] = out; a.mode[0] = 0;
        a.N = DD; a.Kd = HV;
        mmagemmA<4><<<dim3(DD / 128, BT / 128, 1), 256, SMEM4>>>(a);
    }
}

// round 15
// speedup vs baseline: 1.6510x; 1.0234x over previous
#include <cuda_runtime.h>
#include <cuda_bf16.h>
#include <math.h>
#include <stdint.h>

// Problem constants
#define BB 2
#define TT 2048
#define DD 2048
#define HH 16
#define KD 128
#define VD 128
#define BT (BB*TT)          // 4096
#define HK (HH*KD)          // 2048
#define HV (HH*VD)          // 2048

// ---------------- scratch ----------------
__device__ float g_Q[BT*HK];
__device__ float g_K[BT*HK];
__device__ float g_V[BT*HV];
__device__ float g_Qc[BT*HK];
__device__ float g_Kc[BT*HK];
__device__ float g_Vc[BT*HV];
__device__ float g_EG[BT*HK];
__device__ float g_Gate[BT*HV];
__device__ float g_Beta[BT*HH];
__device__ float g_Y[BT*HV];

__device__ __nv_bfloat16 g_xh[BT*DD],  g_xl[BT*DD];
__device__ __nv_bfloat16 g_Yh[BT*HV],  g_Yl[BT*HV];
__device__ __nv_bfloat16 g_F1h[BT*VD], g_F1l[BT*VD];
__device__ __nv_bfloat16 g_G1h[BT*VD], g_G1l[BT*VD];
__device__ __nv_bfloat16 g_Wqh[HK*DD], g_Wql[HK*DD];
__device__ __nv_bfloat16 g_Wkh[HK*DD], g_Wkl[HK*DD];
__device__ __nv_bfloat16 g_Wvh[HV*DD], g_Wvl[HV*DD];
__device__ __nv_bfloat16 g_Woh[DD*HV], g_Wol[DD*HV];
__device__ __nv_bfloat16 g_Wf1h[VD*DD], g_Wf1l[VD*DD];
__device__ __nv_bfloat16 g_Wg1h[VD*DD], g_Wg1l[VD*DD];
__device__ __nv_bfloat16 g_Wf2h[HK*VD], g_Wf2l[HK*VD];
__device__ __nv_bfloat16 g_Wg2h[HV*VD], g_Wg2l[HV*VD];

// ================= helpers =================
#define SWZ(off) ((off) ^ (((off) >> 3) & 0x70))

__device__ __forceinline__ uint32_t sm2u(const void* p) {
    uint32_t a;
    asm("{ .reg .u64 t; cvta.to.shared.u64 t, %1; cvt.u32.u64 %0, t; }" : "=r"(a) : "l"(p));
    return a;
}

#define CP_ASYNC16(dst, src) \
    asm volatile("cp.async.cg.shared.global [%0], [%1], 16;" :: "r"(dst), "l"(src))
#define CP_COMMIT() asm volatile("cp.async.commit_group;")
#define CP_WAIT1()  asm volatile("cp.async.wait_group 1;")
#define CP_WAIT0()  asm volatile("cp.async.wait_group 0;")

#define LDMAT4(r0, r1, r2, r3, addr) \
    asm volatile("ldmatrix.sync.aligned.m8n8.x4.shared.b16 {%0,%1,%2,%3}, [%4];" \
        : "=r"(r0), "=r"(r1), "=r"(r2), "=r"(r3) : "r"(addr))

#define MMA_BF16(d, a, b) \
    asm volatile("mma.sync.aligned.m16n8k16.row.col.f32.bf16.bf16.f32 " \
        "{%0,%1,%2,%3},{%4,%5,%6,%7},{%8,%9},{%0,%1,%2,%3};" \
        : "+f"((d)[0]), "+f"((d)[1]), "+f"((d)[2]), "+f"((d)[3]) \
        : "r"((a)[0]), "r"((a)[1]), "r"((a)[2]), "r"((a)[3]), "r"((b)[0]), "r"((b)[1]))

// packed f32x2 ops
#define FMA2(d, a, b) asm("fma.rn.f32x2 %0, %1, %2, %0;" : "+l"(d) : "l"(a), "l"(b))
#define MUL2(d, a, b) asm("mul.rn.f32x2 %0, %1, %2;" : "=l"(d) : "l"(a), "l"(b))

__device__ __forceinline__ uint64_t pack2(float x, float y) {
    uint64_t r; asm("mov.b64 %0, {%1, %2};" : "=l"(r) : "f"(x), "f"(y)); return r;
}
__device__ __forceinline__ float2 unpack2(uint64_t v) {
    float x, y; asm("mov.b64 {%0, %1}, %2;" : "=f"(x), "=f"(y) : "l"(v));
    return make_float2(x, y);
}

struct BatchArgs {
    const __nv_bfloat16* Ah[3];
    const __nv_bfloat16* Al[3];
    const __nv_bfloat16* Bh[3];
    const __nv_bfloat16* Bl[3];
    float* C[3];
    __nv_bfloat16* Ch[3];
    __nv_bfloat16* Cl[3];
    int mode[3];
    const float* A_log;
    const float* dtb;
    int N, Kd;
};

// fully-unrolled epilogue (MT compile-time -> accumulators stay in registers)
template<int MT, int NT>
__device__ __forceinline__ void gemm_epilogue(const BatchArgs& args, int z,
                                              float acc[MT][NT][4],
                                              int m0, int n0, int mrowbase,
                                              int nw, int lane, int N)
{
    float* __restrict__ C = args.C[z];
    __nv_bfloat16* __restrict__ Ch = args.Ch[z];
    __nv_bfloat16* __restrict__ Cl = args.Cl[z];
    const int mode = args.mode[z];
#pragma unroll
    for (int mt = 0; mt < MT; mt++)
#pragma unroll
        for (int nt = 0; nt < NT; nt++) {
            int r = m0 + mrowbase + mt * 16 + (lane >> 2);
            int c = n0 + nw * NT * 8 + nt * 8 + (lane & 3) * 2;
#pragma unroll
            for (int half = 0; half < 2; half++) {
                int rr = r + half * 8;
                float v0 = acc[mt][nt][half * 2 + 0];
                float v1 = acc[mt][nt][half * 2 + 1];
                size_t off = (size_t)rr * N + c;
                if (mode == 0) {
                    *(float2*)&C[off] = make_float2(v0, v1);
                } else if (mode == 1) {
                    __nv_bfloat16 h0 = __float2bfloat16(v0);
                    __nv_bfloat16 h1 = __float2bfloat16(v1);
                    __nv_bfloat162 hh; hh.x = h0; hh.y = h1;
                    __nv_bfloat162 ll;
                    ll.x = __float2bfloat16(v0 - __bfloat162float(h0));
                    ll.y = __float2bfloat16(v1 - __bfloat162float(h1));
                    *(__nv_bfloat162*)&Ch[off] = hh;
                    *(__nv_bfloat162*)&Cl[off] = ll;
                } else {
                    int h = c >> 7;
                    float ea = expf(args.A_log[h]);
                    float x0 = v0 + args.dtb[c], x1 = v1 + args.dtb[c + 1];
                    float sp0 = (x0 > 20.f) ? x0 : log1pf(expf(x0));
                    float sp1 = (x1 > 20.f) ? x1 : log1pf(expf(x1));
                    *(float2*)&C[off] = make_float2(expf(-ea * sp0), expf(-ea * sp1));
                }
            }
        }
}

// ===== 256-thread variant (8 warps 2x4, mt=4, 3-stage) — best for K=2048 =====
template<int NT>
__global__ __launch_bounds__(256, 1) void mmagemmA(const BatchArgs args)
{
    constexpr int BN  = NT * 32;
    constexpr int WN  = NT * 8;
    constexpr int ASZ = 128 * 128;
    constexpr int BSZ = BN * 128;
    constexpr int STG = 2 * ASZ + 2 * BSZ;
    extern __shared__ __align__(1024) char smem[];
    const uint32_t sb = sm2u(smem);
    const int tid = threadIdx.x;
    const int z = blockIdx.z;
    const int m0 = blockIdx.y * 128, n0 = blockIdx.x * BN;
    const int N = args.N, Kd = args.Kd;

    const __nv_bfloat16* __restrict__ Ah = args.Ah[z];
    const __nv_bfloat16* __restrict__ Al = args.Al[z];
    const __nv_bfloat16* __restrict__ Bh = args.Bh[z];
    const __nv_bfloat16* __restrict__ Bl = args.Bl[z];

    auto prefetch = [&](int stg, int k0) {
        uint32_t b = sb + stg * STG;
        for (int idx = tid; idx < 1024; idx += 256) {
            int row = idx >> 3, ck = idx & 7;
            size_t go = ((size_t)(m0 + row) * Kd + k0) * 2 + ck * 16;
            uint32_t so = b + SWZ(row * 128 + ck * 16);
            CP_ASYNC16(so,       (const char*)Ah + go);
            CP_ASYNC16(so + ASZ, (const char*)Al + go);
        }
        for (int idx = tid; idx < BN * 8; idx += 256) {
            int row = idx >> 3, ck = idx & 7;
            size_t go = ((size_t)(n0 + row) * Kd + k0) * 2 + ck * 16;
            uint32_t so = b + 2 * ASZ + SWZ(row * 128 + ck * 16);
            CP_ASYNC16(so,       (const char*)Bh + go);
            CP_ASYNC16(so + BSZ, (const char*)Bl + go);
        }
    };

    const int wid = tid >> 5, lane = tid & 31;
    const int mw = wid >> 2, nw = wid & 3;
    const uint32_t xm = (lane & 7) * 16;
    const int arow = mw * 64 + (lane & 15);
    const int asel = ((lane >> 4) & 1) << 4;
    const int brow = nw * WN + (lane & 7) + (((lane >> 4) & 1) << 3);
    const int bsel = ((lane >> 3) & 1) << 4;

    float acc[4][NT][4];
#pragma unroll
    for (int mt = 0; mt < 4; mt++)
#pragma unroll
        for (int nt = 0; nt < NT; nt++)
#pragma unroll
            for (int q = 0; q < 4; q++) acc[mt][nt][q] = 0.f;

    const int iters = Kd >> 6;
    prefetch(0, 0);
    CP_COMMIT();
    if (iters > 1) { prefetch(1, 64); }
    CP_COMMIT();
    CP_WAIT1();
    __syncthreads();

    int stg = 0;
    for (int it = 0; it < iters; it++) {
        if (it + 2 < iters) {
            int ns = stg + 2; if (ns >= 3) ns -= 3;
            prefetch(ns, (it + 2) * 64);
            CP_COMMIT();
        }

        const uint32_t b = sb + stg * STG;
#pragma unroll
        for (int kk = 0; kk < 4; kk++) {
            const int koff = kk * 32;
            uint32_t ah[4][4], al[4][4];
#pragma unroll
            for (int mt = 0; mt < 4; mt++) {
                uint32_t ad = b + (uint32_t)(arow + mt * 16) * 128 + ((koff + asel) ^ xm);
                LDMAT4(ah[mt][0], ah[mt][1], ah[mt][2], ah[mt][3], ad);
                LDMAT4(al[mt][0], al[mt][1], al[mt][2], al[mt][3], ad + ASZ);
            }
            uint32_t bh[NT][2], bl[NT][2];
#pragma unroll
            for (int j = 0; j < NT / 2; j++) {
                uint32_t bd = b + 2 * ASZ + (uint32_t)(brow + j * 16) * 128 + ((koff + bsel) ^ xm);
                LDMAT4(bh[2*j][0], bh[2*j][1], bh[2*j+1][0], bh[2*j+1][1], bd);
                LDMAT4(bl[2*j][0], bl[2*j][1], bl[2*j+1][0], bl[2*j+1][1], bd + BSZ);
            }
#pragma unroll
            for (int mt = 0; mt < 4; mt++)
#pragma unroll
                for (int nt = 0; nt < NT; nt++) {
                    MMA_BF16(acc[mt][nt], ah[mt], bh[nt]);
                    MMA_BF16(acc[mt][nt], ah[mt], bl[nt]);
                    MMA_BF16(acc[mt][nt], al[mt], bh[nt]);
                }
        }

        if (it + 1 < iters) { CP_WAIT1(); }
        __syncthreads();
        stg++; if (stg == 3) stg = 0;
    }

    gemm_epilogue<4, NT>(args, z, acc, m0, n0, mw * 64, nw, lane, N);
}

// ===== 512-thread variant (16 warps 4x4, mt=2, 3-stage) — best for K=128 =====
template<int NT>
__global__ __launch_bounds__(512, 1) void mmagemmB(const BatchArgs args)
{
    constexpr int BN  = NT * 32;
    constexpr int WN  = NT * 8;
    constexpr int ASZ = 128 * 128;
    constexpr int BSZ = BN * 128;
    constexpr int STG = 2 * ASZ + 2 * BSZ;
    extern __shared__ __align__(1024) char smem[];
    const uint32_t sb = sm2u(smem);
    const int tid = threadIdx.x;
    const int z = blockIdx.z;
    const int m0 = blockIdx.y * 128, n0 = blockIdx.x * BN;
    const int N = args.N, Kd = args.Kd;

    const __nv_bfloat16* __restrict__ Ah = args.Ah[z];
    const __nv_bfloat16* __restrict__ Al = args.Al[z];
    const __nv_bfloat16* __restrict__ Bh = args.Bh[z];
    const __nv_bfloat16* __restrict__ Bl = args.Bl[z];

    auto prefetch = [&](int stg, int k0) {
        uint32_t b = sb + stg * STG;
#pragma unroll
        for (int idx = tid; idx < 1024; idx += 512) {
            int row = idx >> 3, ck = idx & 7;
            size_t go = ((size_t)(m0 + row) * Kd + k0) * 2 + ck * 16;
            uint32_t so = b + SWZ(row * 128 + ck * 16);
            CP_ASYNC16(so,       (const char*)Ah + go);
            CP_ASYNC16(so + ASZ, (const char*)Al + go);
        }
        for (int idx = tid; idx < BN * 8; idx += 512) {
            int row = idx >> 3, ck = idx & 7;
            size_t go = ((size_t)(n0 + row) * Kd + k0) * 2 + ck * 16;
            uint32_t so = b + 2 * ASZ + SWZ(row * 128 + ck * 16);
            CP_ASYNC16(so,       (const char*)Bh + go);
            CP_ASYNC16(so + BSZ, (const char*)Bl + go);
        }
    };

    const int wid = tid >> 5, lane = tid & 31;
    const int mw = wid >> 2, nw = wid & 3;
    const uint32_t xm = (lane & 7) * 16;
    const int arow = mw * 32 + (lane & 15);
    const int asel = ((lane >> 4) & 1) << 4;
    const int brow = nw * WN + (lane & 7) + (((lane >> 4) & 1) << 3);
    const int bsel = ((lane >> 3) & 1) << 4;

    float acc[2][NT][4];
#pragma unroll
    for (int mt = 0; mt < 2; mt++)
#pragma unroll
        for (int nt = 0; nt < NT; nt++)
#pragma unroll
            for (int q = 0; q < 4; q++) acc[mt][nt][q] = 0.f;

    const int iters = Kd >> 6;
    prefetch(0, 0);
    CP_COMMIT();
    if (iters > 1) { prefetch(1, 64); }
    CP_COMMIT();
    CP_WAIT1();
    __syncthreads();

    int stg = 0;
    for (int it = 0; it < iters; it++) {
        if (it + 2 < iters) {
            int ns = stg + 2; if (ns >= 3) ns -= 3;
            prefetch(ns, (it + 2) * 64);
            CP_COMMIT();
        }

        const uint32_t b = sb + stg * STG;
#pragma unroll
        for (int kk = 0; kk < 4; kk++) {
            const int koff = kk * 32;
            uint32_t ah[2][4], al[2][4];
#pragma unroll
            for (int mt = 0; mt < 2; mt++) {
                uint32_t ad = b + (uint32_t)(arow + mt * 16) * 128 + ((koff + asel) ^ xm);
                LDMAT4(ah[mt][0], ah[mt][1], ah[mt][2], ah[mt][3], ad);
                LDMAT4(al[mt][0], al[mt][1], al[mt][2], al[mt][3], ad + ASZ);
            }
            uint32_t bh[NT][2], bl[NT][2];
#pragma unroll
            for (int j = 0; j < NT / 2; j++) {
                uint32_t bd = b + 2 * ASZ + (uint32_t)(brow + j * 16) * 128 + ((koff + bsel) ^ xm);
                LDMAT4(bh[2*j][0], bh[2*j][1], bh[2*j+1][0], bh[2*j+1][1], bd);
                LDMAT4(bl[2*j][0], bl[2*j][1], bl[2*j+1][0], bl[2*j+1][1], bd + BSZ);
            }
#pragma unroll
            for (int mt = 0; mt < 2; mt++)
#pragma unroll
                for (int nt = 0; nt < NT; nt++) {
                    MMA_BF16(acc[mt][nt], ah[mt], bh[nt]);
                    MMA_BF16(acc[mt][nt], ah[mt], bl[nt]);
                    MMA_BF16(acc[mt][nt], al[mt], bh[nt]);
                }
        }

        if (it + 1 < iters) { CP_WAIT1(); }
        __syncthreads();
        stg++; if (stg == 3) stg = 0;
    }

    gemm_epilogue<2, NT>(args, z, acc, m0, n0, mw * 32, nw, lane, N);
}

// ---------------- fused segmented split ----------------
struct SplitArgs {
    const float4* src[9];
    __nv_bfloat162* h[9];
    __nv_bfloat162* l[9];
    int end[9];
};

__global__ void splitall_kernel(const SplitArgs a)
{
    int bid = blockIdx.x;
    int seg = 0;
#pragma unroll
    for (int i = 0; i < 8; i++)
        if (bid >= a.end[i]) seg = i + 1;
    int start = (seg == 0) ? 0 : a.end[seg - 1];
    int i4 = (bid - start) * 256 + threadIdx.x;
    float4 v = a.src[seg][i4];
    __nv_bfloat16 hx = __float2bfloat16(v.x), hy = __float2bfloat16(v.y);
    __nv_bfloat16 hz = __float2bfloat16(v.z), hw = __float2bfloat16(v.w);
    __nv_bfloat162 p0, p1, q0, q1;
    p0.x = hx; p0.y = hy; p1.x = hz; p1.y = hw;
    q0.x = __float2bfloat16(v.x - __bfloat162float(hx));
    q0.y = __float2bfloat16(v.y - __bfloat162float(hy));
    q1.x = __float2bfloat16(v.z - __bfloat162float(hz));
    q1.y = __float2bfloat16(v.w - __bfloat162float(hw));
    a.h[seg][i4 * 2] = p0; a.h[seg][i4 * 2 + 1] = p1;
    a.l[seg][i4 * 2] = q0; a.l[seg][i4 * 2 + 1] = q1;
}

// ---------------- beta = sigmoid(x @ Wb^T), one row per block (R11 version) ----------------
__global__ __launch_bounds__(256) void beta_kernel(const float* __restrict__ x,
                                                   const float* __restrict__ Wb,
                                                   float* __restrict__ Beta)
{
    const int m = blockIdx.x;
    const int tid = threadIdx.x;
    float acc[HH];
#pragma unroll
    for (int h = 0; h < HH; h++) acc[h] = 0.f;
    for (int d = tid; d < DD; d += 256) {
        float xv = x[(size_t)m * DD + d];
#pragma unroll
        for (int h = 0; h < HH; h++)
            acc[h] = fmaf(xv, Wb[(size_t)h * DD + d], acc[h]);
    }
    __shared__ float red[HH][9];
    const int warp = tid >> 5, lane = tid & 31;
#pragma unroll
    for (int h = 0; h < HH; h++) {
        float v = acc[h];
#pragma unroll
        for (int mask = 16; mask > 0; mask >>= 1)
            v += __shfl_xor_sync(0xffffffffu, v, mask);
        if (lane == 0) red[h][warp] = v;
    }
    __syncthreads();
    if (tid < HH) {
        float s = 0.f;
#pragma unroll
        for (int w = 0; w < 8; w++) s += red[tid][w];
        Beta[(size_t)m * HH + tid] = 1.f / (1.f + expf(-s));
    }
}

// ---------------- causal conv (k=4) + silu (+ l2norm): 8 rows per block ----------------
// grid = (BT/8)*HH. Blocks never straddle a batch boundary (TT % 8 == 0).
__global__ __launch_bounds__(128) void convnorm8_kernel(const float* __restrict__ in,
                                                        const float* __restrict__ w,
                                                        float* __restrict__ out,
                                                        int doNorm)
{
    const int g = blockIdx.x;
    const int h = g & 15;
    const int mg = g >> 4;                 // 0..BT/8-1
    const int m0 = mg * 8;
    const int t0 = m0 & (TT - 1);
    const int c = threadIdx.x;
    const int col = h * 128 + c;
    const float* wp = &w[(size_t)(h * 128 + c) * 4];
    const float w0 = wp[0], w1 = wp[1], w2 = wp[2], w3 = wp[3];

    float x0, x1, x2;
    x0 = (t0 - 3 >= 0) ? in[(size_t)(m0 - 3) * 2048 + col] : 0.f;
    x1 = (t0 - 2 >= 0) ? in[(size_t)(m0 - 2) * 2048 + col] : 0.f;
    x2 = (t0 - 1 >= 0) ? in[(size_t)(m0 - 1) * 2048 + col] : 0.f;

    __shared__ float sred[4];
#pragma unroll
    for (int r = 0; r < 8; r++) {
        float x3 = in[(size_t)(m0 + r) * 2048 + col];
        float acc = fmaf(x0, w0, fmaf(x1, w1, fmaf(x2, w2, x3 * w3)));
        acc = acc / (1.f + expf(-acc));
        if (doNorm) {
            float ss = acc * acc;
#pragma unroll
            for (int mask = 16; mask > 0; mask >>= 1)
                ss += __shfl_xor_sync(0xffffffffu, ss, mask);
            if ((threadIdx.x & 31) == 0) sred[threadIdx.x >> 5] = ss;
            __syncthreads();
            float tot = sred[0] + sred[1] + sred[2] + sred[3];
            acc = acc / fmaxf(sqrtf(tot), 1e-12f);
            __syncthreads();
        }
        out[(size_t)(m0 + r) * 2048 + col] = acc;
        x0 = x1; x1 = x2; x2 = x3;
    }
}

// ---------------- KDA delta-rule scan (128 thr, f32x2, short dot chains) ----------------
#define SCH 16
__global__ __launch_bounds__(128) void scan_kernel(const float* __restrict__ Qc,
                                                   const float* __restrict__ Kc,
                                                   const float* __restrict__ Vc,
                                                   const float* __restrict__ EG,
                                                   const float* __restrict__ Beta,
                                                   float* __restrict__ Y)
{
    const int chunkV = blockIdx.x & 3;
    const int bh = blockIdx.x >> 2;
    const int b = bh >> 4, h = bh & 15;
    const int tid = threadIdx.x;
    const int p = tid & 3;
    const int jj = tid >> 2;
    const int col = h * 128 + chunkV * 32 + jj;

    __shared__ float sk[SCH][144];
    __shared__ float sq[SCH][144];
    __shared__ float se[SCH][144];
    __shared__ float sv[SCH][32];
    __shared__ float sb[SCH];

    uint64_t S2[16];
#pragma unroll
    for (int r = 0; r < 16; r++) S2[r] = 0ull;

    const int pos = tid + ((tid >> 5) << 2);
    const int pbase = p * 36;

    for (int t0 = 0; t0 < TT; t0 += SCH) {
        __syncthreads();
#pragma unroll 4
        for (int s = 0; s < SCH; s++) {
            size_t off = (size_t)(b * TT + t0 + s) * 2048 + h * 128 + tid;
            sk[s][pos] = Kc[off];
            sq[s][pos] = Qc[off];
            se[s][pos] = EG[off];
        }
        if (tid < 32) {
#pragma unroll 4
            for (int s = 0; s < SCH; s++)
                sv[s][tid] = Vc[(size_t)(b * TT + t0 + s) * 2048 + h * 128 + chunkV * 32 + tid];
        }
        if (tid < SCH)
            sb[tid] = Beta[(size_t)(b * TT + t0 + tid) * HH + h];
        __syncthreads();

        for (int s = 0; s < SCH; s++) {
            const float* kp = &sk[s][pbase];
            const float* ep = &se[s][pbase];
            const float* qp = &sq[s][pbase];
            uint64_t k2[16];
            uint64_t d0 = 0ull, d1 = 0ull, d2 = 0ull, d3 = 0ull;
#pragma unroll
            for (int i = 0; i < 8; i++) {
                ulonglong2 kk = *(const ulonglong2*)(kp + 4 * i);
                ulonglong2 ee = *(const ulonglong2*)(ep + 4 * i);
                k2[2 * i] = kk.x; k2[2 * i + 1] = kk.y;
                uint64_t s0, s1;
                MUL2(s0, S2[2 * i],     ee.x);
                MUL2(s1, S2[2 * i + 1], ee.y);
                S2[2 * i] = s0; S2[2 * i + 1] = s1;
                if (i & 1) { FMA2(d2, kk.x, s0); FMA2(d3, kk.y, s1); }
                else       { FMA2(d0, kk.x, s0); FMA2(d1, kk.y, s1); }
            }
            float2 a0 = unpack2(d0), a1 = unpack2(d1), a2 = unpack2(d2), a3 = unpack2(d3);
            float dot = ((a0.x + a0.y) + (a1.x + a1.y)) + ((a2.x + a2.y) + (a3.x + a3.y));
            dot += __shfl_xor_sync(0xffffffffu, dot, 1);
            dot += __shfl_xor_sync(0xffffffffu, dot, 2);
            float u = sb[s] * (sv[s][jj] - dot);
            uint64_t u2 = pack2(u, u);
            uint64_t oa = 0ull, ob = 0ull;
#pragma unroll
            for (int i = 0; i < 8; i++) {
                ulonglong2 qq = *(const ulonglong2*)(qp + 4 * i);
                FMA2(S2[2 * i],     k2[2 * i],     u2);
                FMA2(S2[2 * i + 1], k2[2 * i + 1], u2);
                FMA2(oa, qq.x, S2[2 * i]);
                FMA2(ob, qq.y, S2[2 * i + 1]);
            }
            float2 ov = unpack2(oa), ow = unpack2(ob);
            float od = (ov.x + ov.y) + (ow.x + ow.y);
            od += __shfl_xor_sync(0xffffffffu, od, 1);
            od += __shfl_xor_sync(0xffffffffu, od, 2);
            if (p == 0)
                Y[(size_t)(b * TT + t0 + s) * 2048 + col] = od;
        }
    }
}

// ---------------- RMS norm + gate, 8 (m,h) pairs per block ----------------
__global__ __launch_bounds__(128) void rmsgate8_kernel(const float* __restrict__ Y,
                                                       const float* __restrict__ Gate,
                                                       const float* __restrict__ bg,
                                                       const float* __restrict__ onw,
                                                       __nv_bfloat16* __restrict__ Yh,
                                                       __nv_bfloat16* __restrict__ Yl)
{
    const int c = threadIdx.x;
    __shared__ float sred[4];
    const float ow = onw[c];
#pragma unroll
    for (int r = 0; r < 8; r++) {
        const int gidx = blockIdx.x * 8 + r;          // (m*16 + h)
        const int m = gidx >> 4;
        const int h = gidx & 15;
        const int col = h * 128 + c;
        float y = Y[(size_t)m * 2048 + col];
        float ss = y * y;
#pragma unroll
        for (int mask = 16; mask > 0; mask >>= 1)
            ss += __shfl_xor_sync(0xffffffffu, ss, mask);
        if ((threadIdx.x & 31) == 0) sred[threadIdx.x >> 5] = ss;
        __syncthreads();
        float tot = sred[0] + sred[1] + sred[2] + sred[3];
        float rr = rsqrtf(tot * (1.f / 128.f) + 1.1920929e-07f);
        float g = Gate[(size_t)m * 2048 + col] + bg[col];
        float v = y * rr * ow / (1.f + expf(-g));
        __nv_bfloat16 vh = __float2bfloat16(v);
        Yh[(size_t)m * 2048 + col] = vh;
        Yl[(size_t)m * 2048 + col] = __float2bfloat16(v - __bfloat162float(vh));
        __syncthreads();
    }
}

// ---------------- host ----------------
extern "C" void kernel_launch(void* const* d_in, const int* in_sizes, int n_in,
                              void* d_out, int out_size)
{
    const float* x     = (const float*)d_in[0];
    const float* Wq    = (const float*)d_in[1];
    const float* Wk    = (const float*)d_in[2];
    const float* Wv    = (const float*)d_in[3];
    const float* Wf1   = (const float*)d_in[4];
    const float* Wf2   = (const float*)d_in[5];
    const float* Wb    = (const float*)d_in[6];
    const float* Wg1   = (const float*)d_in[7];
    const float* Wg2   = (const float*)d_in[8];
    const float* bg    = (const float*)d_in[9];
    const float* onw   = (const float*)d_in[10];
    const float* Wout  = (const float*)d_in[11];
    const float* A_log = (const float*)d_in[12];
    const float* dtb   = (const float*)d_in[13];
    const float* qcw   = (const float*)d_in[14];
    const float* kcw   = (const float*)d_in[15];
    const float* vcw   = (const float*)d_in[16];
    float* out = (float*)d_out;

    float *Q, *K, *V, *Qc, *Kc, *Vc, *EG, *Gate, *Beta, *Y;
    cudaGetSymbolAddress((void**)&Q,   g_Q);
    cudaGetSymbolAddress((void**)&K,   g_K);
    cudaGetSymbolAddress((void**)&V,   g_V);
    cudaGetSymbolAddress((void**)&Qc,  g_Qc);
    cudaGetSymbolAddress((void**)&Kc,  g_Kc);
    cudaGetSymbolAddress((void**)&Vc,  g_Vc);
    cudaGetSymbolAddress((void**)&EG,  g_EG);
    cudaGetSymbolAddress((void**)&Gate,g_Gate);
    cudaGetSymbolAddress((void**)&Beta,g_Beta);
    cudaGetSymbolAddress((void**)&Y,   g_Y);

    __nv_bfloat16 *xh,*xl,*Yh,*Yl,*F1h,*F1l,*G1h,*G1l;
    __nv_bfloat16 *Wqh,*Wql,*Wkh,*Wkl,*Wvh,*Wvl,*Woh,*Wol;
    __nv_bfloat16 *Wf1h,*Wf1l,*Wg1h,*Wg1l,*Wf2h,*Wf2l,*Wg2h,*Wg2l;
    cudaGetSymbolAddress((void**)&xh, g_xh);   cudaGetSymbolAddress((void**)&xl, g_xl);
    cudaGetSymbolAddress((void**)&Yh, g_Yh);   cudaGetSymbolAddress((void**)&Yl, g_Yl);
    cudaGetSymbolAddress((void**)&F1h, g_F1h); cudaGetSymbolAddress((void**)&F1l, g_F1l);
    cudaGetSymbolAddress((void**)&G1h, g_G1h); cudaGetSymbolAddress((void**)&G1l, g_G1l);
    cudaGetSymbolAddress((void**)&Wqh, g_Wqh); cudaGetSymbolAddress((void**)&Wql, g_Wql);
    cudaGetSymbolAddress((void**)&Wkh, g_Wkh); cudaGetSymbolAddress((void**)&Wkl, g_Wkl);
    cudaGetSymbolAddress((void**)&Wvh, g_Wvh); cudaGetSymbolAddress((void**)&Wvl, g_Wvl);
    cudaGetSymbolAddress((void**)&Woh, g_Woh); cudaGetSymbolAddress((void**)&Wol, g_Wol);
    cudaGetSymbolAddress((void**)&Wf1h, g_Wf1h); cudaGetSymbolAddress((void**)&Wf1l, g_Wf1l);
    cudaGetSymbolAddress((void**)&Wg1h, g_Wg1h); cudaGetSymbolAddress((void**)&Wg1l, g_Wg1l);
    cudaGetSymbolAddress((void**)&Wf2h, g_Wf2h); cudaGetSymbolAddress((void**)&Wf2l, g_Wf2l);
    cudaGetSymbolAddress((void**)&Wg2h, g_Wg2h); cudaGetSymbolAddress((void**)&Wg2l, g_Wg2l);

    const int SMEM4 = 3 * (2 * 128 * 128 + 2 * 128 * 128);   // 196608 (NT=4)
    const int SMEM2 = 3 * (2 * 128 * 128 + 2 * 64 * 128);    // 147456 (NT=2)
    cudaFuncSetAttribute(mmagemmA<4>, cudaFuncAttributeMaxDynamicSharedMemorySize, SMEM4);
    cudaFuncSetAttribute(mmagemmA<2>, cudaFuncAttributeMaxDynamicSharedMemorySize, SMEM2);
    cudaFuncSetAttribute(mmagemmB<4>, cudaFuncAttributeMaxDynamicSharedMemorySize, SMEM4);

    // launch #1: all fp32->bf16 splits, one segmented kernel
    {
        SplitArgs sa{};
        const float* srcs[9] = {x, Wq, Wk, Wv, Wout, Wf1, Wg1, Wf2, Wg2};
        __nv_bfloat16* hs[9] = {xh, Wqh, Wkh, Wvh, Woh, Wf1h, Wg1h, Wf2h, Wg2h};
        __nv_bfloat16* ls[9] = {xl, Wql, Wkl, Wvl, Wol, Wf1l, Wg1l, Wf2l, Wg2l};
        const int elems[9] = {BT*DD, HK*DD, HK*DD, HV*DD, DD*HV, VD*DD, VD*DD, HK*VD, HV*VD};
        int cum = 0;
        for (int i = 0; i < 9; i++) {
            sa.src[i] = (const float4*)srcs[i];
            sa.h[i] = (__nv_bfloat162*)hs[i];
            sa.l[i] = (__nv_bfloat162*)ls[i];
            cum += elems[i] / 1024;
            sa.end[i] = cum;
        }
        splitall_kernel<<<cum, 256>>>(sa);
    }

    // launch #2: batched QKV projection (K=2048 -> 256-thread variant)
    {
        BatchArgs a{};
        for (int z = 0; z < 3; z++) { a.Ah[z] = xh; a.Al[z] = xl; a.mode[z] = 0; }
        a.Bh[0] = Wqh; a.Bl[0] = Wql; a.C[0] = Q;
        a.Bh[1] = Wkh; a.Bl[1] = Wkl; a.C[1] = K;
        a.Bh[2] = Wvh; a.Bl[2] = Wvl; a.C[2] = V;
        a.N = HK; a.Kd = DD;
        mmagemmA<4><<<dim3(HK / 128, BT / 128, 3), 256, SMEM4>>>(a);
    }

    // launch #3: batched F1/G1 (K=2048 -> 256-thread variant)
    {
        BatchArgs a{};
        for (int z = 0; z < 2; z++) { a.Ah[z] = xh; a.Al[z] = xl; a.mode[z] = 1; }
        a.Bh[0] = Wf1h; a.Bl[0] = Wf1l; a.Ch[0] = F1h; a.Cl[0] = F1l;
        a.Bh[1] = Wg1h; a.Bl[1] = Wg1l; a.Ch[1] = G1h; a.Cl[1] = G1l;
        a.N = VD; a.Kd = DD;
        mmagemmA<2><<<dim3(VD / 64, BT / 128, 2), 256, SMEM2>>>(a);
    }

    // launch #4: batched EG (decay fused) + Gate (K=128 -> 512-thread variant)
    {
        BatchArgs a{};
        a.Ah[0] = F1h; a.Al[0] = F1l; a.Bh[0] = Wf2h; a.Bl[0] = Wf2l; a.C[0] = EG;   a.mode[0] = 2;
        a.Ah[1] = G1h; a.Al[1] = G1l; a.Bh[1] = Wg2h; a.Bl[1] = Wg2l; a.C[1] = Gate; a.mode[1] = 0;
        a.A_log = A_log; a.dtb = dtb;
        a.N = HK; a.Kd = VD;
        mmagemmB<4><<<dim3(HK / 128, BT / 128, 2), 512, SMEM4>>>(a);
    }

    beta_kernel<<<BT, 256>>>(x, Wb, Beta);

    convnorm8_kernel<<<(BT / 8) * HH, 128>>>(Q, qcw, Qc, 1);
    convnorm8_kernel<<<(BT / 8) * HH, 128>>>(K, kcw, Kc, 1);
    convnorm8_kernel<<<(BT / 8) * HH, 128>>>(V, vcw, Vc, 0);

    scan_kernel<<<BB * HH * 4, 128>>>(Qc, Kc, Vc, EG, Beta, Y);

    rmsgate8_kernel<<<BT * HH / 8, 128>>>(Y, Gate, bg, onw, Yh, Yl);

    // out projection (K=2048 -> 256-thread variant)
    {
        BatchArgs a{};
        a.Ah[0] = Yh; a.Al[0] = Yl; a.Bh[0] = Woh; a.Bl[0] = Wol; a.C[0] = out; a.mode[0] = 0;
        a.N = DD; a.Kd = HV;
        mmagemmA<4><<<dim3(DD / 128, BT / 128, 1), 256, SMEM4>>>(a);
    }
}